// round 3
// baseline (speedup 1.0000x reference)
#include <cuda_runtime.h>
#include <math.h>

// Problem constants (b=2, c=64, H=480, W=640, gs=8 -> hc=60, wc=80, n=4800)
#define BQ 2
#define CC 64
#define HC 60
#define WCC 80
#define NN 4800
#define HH 480
#define WW 640
#define EPSF 1e-8f

// Main GEMM tiling: 128 threads = 16 row-threads x 8 col-threads,
// thread tile 4 rows x 8 cols -> block tile 64 rows x 64 cols.
#define BR 64
#define BC 64
#define NTPC 5                        // col tiles per chunk
#define NCH 15                        // chunks: 15*5*64 = 4800 cols
#define ROWB (NN / BR)                // 75
#define TOTALB (NCH * ROWB * BQ)      // 2250

typedef unsigned long long ull;

// ---------------- scratch (no allocations allowed) ----------------
__device__ float    g_visPen[BQ * NN];   // (1 - cell_vis) * 5 in {0,5}
__device__ float    g_posSim[BQ * NN];
__device__ float    g_match[BQ * NN];
__device__ int      g_neigh[BQ * NN * 4];
__device__ int      g_negMinI[BQ * NN];  // per-row min as int-cast positive float
__device__ unsigned g_ctr;

// ---------------- packed f32x2 helpers ----------------
__device__ __forceinline__ void unpack2(ull v, float &x, float &y) {
    asm("mov.b64 {%0,%1},%2;" : "=f"(x), "=f"(y) : "l"(v));
}
__device__ __forceinline__ void ffma2(ull &d, ull a, ull b) {
    asm("fma.rn.f32x2 %0,%1,%2,%0;" : "+l"(d) : "l"(a), "l"(b));
}

__device__ __forceinline__ float inb_pix(float yi, float xi) {
    return (yi >= 0.f && yi <= (float)(HH - 1) && xi >= 0.f && xi <= (float)(WW - 1)) ? 1.f : 0.f;
}
__device__ __forceinline__ float inb_grid(float yi, float xi) {
    return (yi >= 0.f && yi <= (float)(HC - 1) && xi >= 0.f && xi <= (float)(WCC - 1)) ? 1.f : 0.f;
}

// ====== Kernel 0: per-row prep (warp per row): vis, 4-NN, posSim, match, init
__global__ void prep_kernel(const float* __restrict__ desc1,
                            const float* __restrict__ desc2,
                            const float* __restrict__ homo12,
                            const float* __restrict__ homo21) {
    if (blockIdx.x == 0 && threadIdx.x == 0) g_ctr = 0u;
    int w = blockIdx.x * 8 + (threadIdx.x >> 5);
    if (w >= BQ * NN) return;
    int lane = threadIdx.x & 31;
    int b = w / NN, r = w % NN;
    int iy = r / WCC, ix = r % WCC;

    // ---- visibility of the 8x8 cell under homo21 ----
    {
        const float* h = homo21 + b * 9;
        float h0 = h[0], h1 = h[1], h2 = h[2], h3 = h[3], h4 = h[4],
              h5 = h[5], h6 = h[6], h7 = h[7], h8 = h[8];
        bool ok = true;
#pragma unroll
        for (int pp = 0; pp < 2; ++pp) {
            int p = lane + pp * 32;
            float x = (float)(ix * 8 + (p & 7));
            float y = (float)(iy * 8 + (p >> 3));
            float qx = h0 * x + h1 * y + h2;
            float qy = h3 * x + h4 * y + h5;
            float qz = h6 * x + h7 * y + h8;
            float wx = qx / (qz + EPSF);
            float wy = qy / (qz + EPSF);
            float y0 = floorf(wy), x0 = floorf(wx);
            float fy = wy - y0, fx = wx - x0;
            float val = (1.f - fy) * (1.f - fx) * inb_pix(y0, x0)
                      + (1.f - fy) * fx         * inb_pix(y0, x0 + 1.f)
                      + fy * (1.f - fx)         * inb_pix(y0 + 1.f, x0)
                      + fy * fx                 * inb_pix(y0 + 1.f, x0 + 1.f);
            ok = ok && (val > 0.f);
        }
        unsigned all = __all_sync(0xffffffffu, ok);
        if (lane == 0) {
            g_visPen[b * NN + r] = all ? 0.f : 5.f;
            g_negMinI[b * NN + r] = 0x7F800000;   // +inf
        }
    }

    // ---- warp point under homo12 ----
    const float* h = homo12 + b * 9;
    float px = (float)(ix * 8) + 3.5f;
    float py = (float)(iy * 8) + 3.5f;
    float qx = h[0] * px + h[1] * py + h[2];
    float qy = h[3] * px + h[4] * py + h[5];
    float qz = h[6] * px + h[7] * py + h[8];
    float wx = qx / (qz + EPSF);
    float wy = qy / (qz + EPSF);
    float dyc = (wy - 3.5f) * 0.125f;
    float dxc = (wx - 3.5f) * 0.125f;

    // ---- bilinear w_desc1, pos_sim (2 channels per lane) ----
    float y0 = floorf(dyc), x0 = floorf(dxc);
    float fy = dyc - y0, fx = dxc - x0;
    float e00 = (1.f - fy) * (1.f - fx) * inb_grid(y0, x0);
    float e01 = (1.f - fy) * fx         * inb_grid(y0, x0 + 1.f);
    float e10 = fy * (1.f - fx)         * inb_grid(y0 + 1.f, x0);
    float e11 = fy * fx                 * inb_grid(y0 + 1.f, x0 + 1.f);
    int yc0 = (int)fminf(fmaxf(y0, 0.f), (float)(HC - 1));
    int yc1 = (int)fminf(fmaxf(y0 + 1.f, 0.f), (float)(HC - 1));
    int xc0 = (int)fminf(fmaxf(x0, 0.f), (float)(WCC - 1));
    int xc1 = (int)fminf(fmaxf(x0 + 1.f, 0.f), (float)(WCC - 1));

    float sq = 0.f, dp = 0.f;
#pragma unroll
    for (int pp = 0; pp < 2; ++pp) {
        int ch = lane + 32 * pp;
        const float* base = desc2 + (size_t)(b * CC + ch) * NN;
        float v = e00 * base[yc0 * WCC + xc0] + e01 * base[yc0 * WCC + xc1]
                + e10 * base[yc1 * WCC + xc0] + e11 * base[yc1 * WCC + xc1];
        sq += v * v;
        dp += desc1[(size_t)(b * CC + ch) * NN + r] * v;
    }
#pragma unroll
    for (int off = 16; off; off >>= 1) {
        sq += __shfl_xor_sync(0xffffffffu, sq, off);
        dp += __shfl_xor_sync(0xffffffffu, dp, off);
    }

    if (lane == 0) {
        float posdot = dp / (sqrtf(sq) + EPSF);
        g_posSim[b * NN + r] = sqrtf(fmaxf(2.f - 2.f * posdot, EPSF));
        g_match[b * NN + r] =
            (wy >= 0.f && wy <= (float)(HH - 1) && wx >= 0.f && wx <= (float)(WW - 1)) ? 1.f : 0.f;

        // 4 nearest grid centers (tie -> lower index), in clamped 4x4 window
        float a2 = wy * wy + wx * wx;
        int xlo = (int)fminf(fmaxf(floorf(dxc) - 1.f, 0.f), (float)(WCC - 4));
        int ylo = (int)fminf(fmaxf(floorf(dyc) - 1.f, 0.f), (float)(HC - 4));
        float bd[4] = {1e30f, 1e30f, 1e30f, 1e30f};
        int bi[4] = {-1, -1, -1, -1};
#pragma unroll
        for (int jy = 0; jy < 4; ++jy) {
            int iyc = ylo + jy;
            float cy = (float)(iyc * 8) + 3.5f;
#pragma unroll
            for (int jx = 0; jx < 4; ++jx) {
                int ixc = xlo + jx;
                float cx = (float)(ixc * 8) + 3.5f;
                float d = sqrtf(fmaxf(a2 + cy * cy + cx * cx - 2.f * (wy * cy + wx * cx), 0.f));
                int m = iyc * WCC + ixc;
                if (d < bd[3]) {
                    int k = 3;
                    while (k > 0 && d < bd[k - 1]) {
                        bd[k] = bd[k - 1]; bi[k] = bi[k - 1]; --k;
                    }
                    bd[k] = d; bi[k] = m;
                }
            }
        }
        int* o = &g_neigh[(size_t)(b * NN + r) * 4];
        o[0] = bi[0]; o[1] = bi[1]; o[2] = bi[2]; o[3] = bi[3];
    }
}

// ====== Kernel 1: n x n desc_sim row-min, register-tiled f32x2 GEMM ======
__global__ void __launch_bounds__(128, 3)
main_kernel(const float* __restrict__ desc1, const float* __restrict__ desc2,
            float* __restrict__ out) {
    __shared__ __align__(16) float2 a_s[32][BR];   // 16 KB: (chan-pair, row)
    __shared__ __align__(16) float2 b_s[32][BC];   // 16 KB: (chan-pair, col)
    __shared__ __align__(16) float vs[BC];
    __shared__ int s_last;
    __shared__ float rL[4], rM[4];

    int tid = threadIdx.x;
    int rt = tid >> 3;      // 0..15
    int ct = tid & 7;       // 0..7
    int chunk = blockIdx.x; // 0..14
    int row0 = blockIdx.y * BR;
    int b = blockIdx.z;

    // ---- stage A tile once: 64 rows x 64 channels ----
    {
        int i = tid;
#pragma unroll
        for (int k = 0; k < (BR * CC) / 128; ++k) {
            int ch = i >> 6, rr = i & 63;
            float v = desc1[(size_t)(b * CC + ch) * NN + row0 + rr];
            reinterpret_cast<float*>(&a_s[ch >> 1][rr])[ch & 1] = v;
            i += 128;
        }
    }

    // neighbor indices for my 4 rows
    int nb[16];
#pragma unroll
    for (int rr = 0; rr < 4; ++rr) {
        int4 q = *reinterpret_cast<const int4*>(
            &g_neigh[(size_t)(b * NN + row0 + rt * 4 + rr) * 4]);
        nb[rr * 4 + 0] = q.x; nb[rr * 4 + 1] = q.y;
        nb[rr * 4 + 2] = q.z; nb[rr * 4 + 3] = q.w;
    }

    float tmin[4] = {1e30f, 1e30f, 1e30f, 1e30f};
    float smin[4] = {1e30f, 1e30f, 1e30f, 1e30f};

    for (int t = 0; t < NTPC; ++t) {
        int colbase = (chunk * NTPC + t) * BC;
        // stage B tile
        {
            int i = tid;
#pragma unroll
            for (int k = 0; k < (BC * CC) / 128; ++k) {
                int ch = i >> 6, cc2 = i & 63;
                float v = desc2[(size_t)(b * CC + ch) * NN + colbase + cc2];
                reinterpret_cast<float*>(&b_s[ch >> 1][cc2])[ch & 1] = v;
                i += 128;
            }
        }
        if (tid < BC) vs[tid] = g_visPen[b * NN + colbase + tid];
        __syncthreads();

        ull acc[32];
#pragma unroll
        for (int z = 0; z < 32; ++z) acc[z] = 0ull;

#pragma unroll 2
        for (int cp = 0; cp < 32; ++cp) {
            ulonglong2 a01 = *reinterpret_cast<const ulonglong2*>(&a_s[cp][rt * 4]);
            ulonglong2 a23 = *reinterpret_cast<const ulonglong2*>(&a_s[cp][rt * 4 + 2]);
            ulonglong2 b01 = *reinterpret_cast<const ulonglong2*>(&b_s[cp][ct * 8]);
            ulonglong2 b23 = *reinterpret_cast<const ulonglong2*>(&b_s[cp][ct * 8 + 2]);
            ulonglong2 b45 = *reinterpret_cast<const ulonglong2*>(&b_s[cp][ct * 8 + 4]);
            ulonglong2 b67 = *reinterpret_cast<const ulonglong2*>(&b_s[cp][ct * 8 + 6]);
            ull av[4] = {a01.x, a01.y, a23.x, a23.y};
            ull bv[8] = {b01.x, b01.y, b23.x, b23.y, b45.x, b45.y, b67.x, b67.y};
#pragma unroll
            for (int rr = 0; rr < 4; ++rr)
#pragma unroll
                for (int c = 0; c < 8; ++c)
                    ffma2(acc[rr * 8 + c], av[rr], bv[c]);
        }

        // per-tile epilogue: dual-track min
        float4 vpA = *reinterpret_cast<const float4*>(&vs[ct * 8]);
        float4 vpB = *reinterpret_cast<const float4*>(&vs[ct * 8 + 4]);
        float vp[8] = {vpA.x, vpA.y, vpA.z, vpA.w, vpB.x, vpB.y, vpB.z, vpB.w};
        int cb = colbase + ct * 8;
#pragma unroll
        for (int rr = 0; rr < 4; ++rr) {
            unsigned nm = 0;
#pragma unroll
            for (int j = 0; j < 4; ++j) {
                int off = nb[rr * 4 + j] - cb;
                if ((unsigned)off < 8u) nm |= 1u << off;
            }
#pragma unroll
            for (int c = 0; c < 8; ++c) {
                float x, y; unpack2(acc[rr * 8 + c], x, y);
                float tt = 2.0f - 2.0f * (x + y);
                float pen = vp[c] + (((nm >> c) & 1u) ? 5.0f : 0.0f);
                if (pen == 0.0f) {
                    tmin[rr] = fminf(tmin[rr], tt);
                } else {
                    smin[rr] = fminf(smin[rr], sqrtf(fmaxf(tt, EPSF)) + pen);
                }
            }
        }
        __syncthreads();
    }

    // reduce across the 8 col-threads (lane bits 0..2) and commit
#pragma unroll
    for (int rr = 0; rr < 4; ++rr) {
        float v = fminf(sqrtf(fmaxf(tmin[rr], EPSF)), smin[rr]);
#pragma unroll
        for (int off = 4; off; off >>= 1)
            v = fminf(v, __shfl_xor_sync(0xffffffffu, v, off));
        if (ct == 0)
            atomicMin(&g_negMinI[b * NN + row0 + rt * 4 + rr], __float_as_int(v));
    }

    // ---- last block: deterministic final reduction ----
    __syncthreads();
    if (tid == 0) {
        __threadfence();
        s_last = (atomicAdd(&g_ctr, 1u) == TOTALB - 1) ? 1 : 0;
    }
    __syncthreads();
    if (s_last) {
        __threadfence();
        float aL = 0.f, aM = 0.f;
        for (int i = tid; i < BQ * NN; i += 128) {
            float neg = __int_as_float(g_negMinI[i]);
            float l = fmaxf(g_posSim[i] - neg + 1.0f, 0.f);
            float m = g_match[i];
            aL += l * l * m;
            aM += m;
        }
#pragma unroll
        for (int off = 16; off; off >>= 1) {
            aL += __shfl_xor_sync(0xffffffffu, aL, off);
            aM += __shfl_xor_sync(0xffffffffu, aM, off);
        }
        if ((tid & 31) == 0) { rL[tid >> 5] = aL; rM[tid >> 5] = aM; }
        __syncthreads();
        if (tid == 0) {
            float sL = 0.f, sM = 0.f;
#pragma unroll
            for (int wnum = 0; wnum < 4; ++wnum) { sL += rL[wnum]; sM += rM[wnum]; }
            out[0] = sL / sM;
        }
    }
}

// ---------------- launch ----------------
extern "C" void kernel_launch(void* const* d_in, const int* in_sizes, int n_in,
                              void* d_out, int out_size) {
    // metadata order: score1, score2, desc1, desc2, homo12, homo21
    const float* desc1  = (const float*)d_in[2];
    const float* desc2  = (const float*)d_in[3];
    const float* homo12 = (const float*)d_in[4];
    const float* homo21 = (const float*)d_in[5];

    prep_kernel<<<(BQ * NN + 7) / 8, 256>>>(desc1, desc2, homo12, homo21);
    dim3 g(NCH, ROWB, BQ);
    main_kernel<<<g, 128>>>(desc1, desc2, (float*)d_out);
}

// round 4
// speedup vs baseline: 2.5008x; 2.5008x over previous
#include <cuda_runtime.h>
#include <math.h>

// Problem constants (b=2, c=64, H=480, W=640, gs=8 -> hc=60, wc=80, n=4800)
#define BQ 2
#define CC 64
#define HC 60
#define WCC 80
#define NN 4800
#define HH 480
#define WW 640
#define EPSF 1e-8f
#define NEGBIG -1e30f

// Main GEMM tiling: 128 threads = 16 rt x 8 ct, thread tile 8x8 (f32x2 accs)
// block tile 128 rows x 64 cols; 15 col-chunks x 5 tiles x 64 = 4800 cols
#define NTPC 5
#define NCH 15
#define ROWB ((NN + 127) / 128)        // 38 (last block rows 4736..4863, guarded)
#define TOTALB (NCH * ROWB * BQ)       // 1140

// padded smem layout: 64B data chunks at 80B stride (conflict-free LDS.128)
#define A_CP_STRIDE 1280               // 16 rt-chunks * 80
#define B_CP_STRIDE 640                // 8 ct-chunks * 80
#define A_BYTES (32 * A_CP_STRIDE)     // 40960
#define B_BYTES (32 * B_CP_STRIDE)     // 20480
#define SMEM_BYTES (A_BYTES + B_BYTES + 64 * 4)  // 61696

typedef unsigned long long ull;

// ---------------- scratch (no allocations allowed) ----------------
__device__ float    g_visNeg[BQ * NN];   // 0 if cell visible else -1e30
__device__ float    g_posSim[BQ * NN];
__device__ float    g_match[BQ * NN];
__device__ int      g_neigh[BQ * NN * 4];
__device__ int      g_negMinI[BQ * NN];  // per-row min as int-cast positive float
__device__ unsigned g_ctr;

__device__ __forceinline__ void unpack2(ull v, float &x, float &y) {
    asm("mov.b64 {%0,%1},%2;" : "=f"(x), "=f"(y) : "l"(v));
}
__device__ __forceinline__ void ffma2(ull &d, ull a, ull b) {
    asm("fma.rn.f32x2 %0,%1,%2,%0;" : "+l"(d) : "l"(a), "l"(b));
}
__device__ __forceinline__ float inb_pix(float yi, float xi) {
    return (yi >= 0.f && yi <= (float)(HH - 1) && xi >= 0.f && xi <= (float)(WW - 1)) ? 1.f : 0.f;
}
__device__ __forceinline__ float inb_grid(float yi, float xi) {
    return (yi >= 0.f && yi <= (float)(HC - 1) && xi >= 0.f && xi <= (float)(WCC - 1)) ? 1.f : 0.f;
}

// ====== Kernel 0: per-row prep (warp per row): vis, 4-NN, posSim, match, init
__global__ void prep_kernel(const float* __restrict__ desc1,
                            const float* __restrict__ desc2,
                            const float* __restrict__ homo12,
                            const float* __restrict__ homo21) {
    if (blockIdx.x == 0 && threadIdx.x == 0) g_ctr = 0u;
    int w = blockIdx.x * 8 + (threadIdx.x >> 5);
    if (w >= BQ * NN) return;
    int lane = threadIdx.x & 31;
    int b = w / NN, r = w % NN;
    int iy = r / WCC, ix = r % WCC;

    // ---- visibility of the 8x8 cell under homo21 ----
    {
        const float* h = homo21 + b * 9;
        float h0 = h[0], h1 = h[1], h2 = h[2], h3 = h[3], h4 = h[4],
              h5 = h[5], h6 = h[6], h7 = h[7], h8 = h[8];
        bool ok = true;
#pragma unroll
        for (int pp = 0; pp < 2; ++pp) {
            int p = lane + pp * 32;
            float x = (float)(ix * 8 + (p & 7));
            float y = (float)(iy * 8 + (p >> 3));
            float qx = h0 * x + h1 * y + h2;
            float qy = h3 * x + h4 * y + h5;
            float qz = h6 * x + h7 * y + h8;
            float wx = qx / (qz + EPSF);
            float wy = qy / (qz + EPSF);
            float y0 = floorf(wy), x0 = floorf(wx);
            float fy = wy - y0, fx = wx - x0;
            float val = (1.f - fy) * (1.f - fx) * inb_pix(y0, x0)
                      + (1.f - fy) * fx         * inb_pix(y0, x0 + 1.f)
                      + fy * (1.f - fx)         * inb_pix(y0 + 1.f, x0)
                      + fy * fx                 * inb_pix(y0 + 1.f, x0 + 1.f);
            ok = ok && (val > 0.f);
        }
        unsigned all = __all_sync(0xffffffffu, ok);
        if (lane == 0) {
            g_visNeg[b * NN + r] = all ? 0.f : NEGBIG;
            g_negMinI[b * NN + r] = 0x7F800000;   // +inf
        }
    }

    // ---- warp point under homo12 ----
    const float* h = homo12 + b * 9;
    float px = (float)(ix * 8) + 3.5f;
    float py = (float)(iy * 8) + 3.5f;
    float qx = h[0] * px + h[1] * py + h[2];
    float qy = h[3] * px + h[4] * py + h[5];
    float qz = h[6] * px + h[7] * py + h[8];
    float wx = qx / (qz + EPSF);
    float wy = qy / (qz + EPSF);
    float dyc = (wy - 3.5f) * 0.125f;
    float dxc = (wx - 3.5f) * 0.125f;

    // ---- bilinear w_desc1, pos_sim (2 channels per lane) ----
    float y0 = floorf(dyc), x0 = floorf(dxc);
    float fy = dyc - y0, fx = dxc - x0;
    float e00 = (1.f - fy) * (1.f - fx) * inb_grid(y0, x0);
    float e01 = (1.f - fy) * fx         * inb_grid(y0, x0 + 1.f);
    float e10 = fy * (1.f - fx)         * inb_grid(y0 + 1.f, x0);
    float e11 = fy * fx                 * inb_grid(y0 + 1.f, x0 + 1.f);
    int yc0 = (int)fminf(fmaxf(y0, 0.f), (float)(HC - 1));
    int yc1 = (int)fminf(fmaxf(y0 + 1.f, 0.f), (float)(HC - 1));
    int xc0 = (int)fminf(fmaxf(x0, 0.f), (float)(WCC - 1));
    int xc1 = (int)fminf(fmaxf(x0 + 1.f, 0.f), (float)(WCC - 1));

    float sq = 0.f, dp = 0.f;
#pragma unroll
    for (int pp = 0; pp < 2; ++pp) {
        int ch = lane + 32 * pp;
        const float* base = desc2 + (size_t)(b * CC + ch) * NN;
        float v = e00 * base[yc0 * WCC + xc0] + e01 * base[yc0 * WCC + xc1]
                + e10 * base[yc1 * WCC + xc0] + e11 * base[yc1 * WCC + xc1];
        sq += v * v;
        dp += desc1[(size_t)(b * CC + ch) * NN + r] * v;
    }
#pragma unroll
    for (int off = 16; off; off >>= 1) {
        sq += __shfl_xor_sync(0xffffffffu, sq, off);
        dp += __shfl_xor_sync(0xffffffffu, dp, off);
    }

    if (lane == 0) {
        float posdot = dp / (sqrtf(sq) + EPSF);
        g_posSim[b * NN + r] = sqrtf(fmaxf(2.f - 2.f * posdot, EPSF));
        g_match[b * NN + r] =
            (wy >= 0.f && wy <= (float)(HH - 1) && wx >= 0.f && wx <= (float)(WW - 1)) ? 1.f : 0.f;

        // 4 nearest grid centers (tie -> lower index), in clamped 4x4 window
        float a2 = wy * wy + wx * wx;
        int xlo = (int)fminf(fmaxf(floorf(dxc) - 1.f, 0.f), (float)(WCC - 4));
        int ylo = (int)fminf(fmaxf(floorf(dyc) - 1.f, 0.f), (float)(HC - 4));
        float bd[4] = {1e30f, 1e30f, 1e30f, 1e30f};
        int bi[4] = {-1, -1, -1, -1};
#pragma unroll
        for (int jy = 0; jy < 4; ++jy) {
            int iyc = ylo + jy;
            float cy = (float)(iyc * 8) + 3.5f;
#pragma unroll
            for (int jx = 0; jx < 4; ++jx) {
                int ixc = xlo + jx;
                float cx = (float)(ixc * 8) + 3.5f;
                float d = sqrtf(fmaxf(a2 + cy * cy + cx * cx - 2.f * (wy * cy + wx * cx), 0.f));
                int m = iyc * WCC + ixc;
                if (d < bd[3]) {
                    int k = 3;
                    while (k > 0 && d < bd[k - 1]) {
                        bd[k] = bd[k - 1]; bi[k] = bi[k - 1]; --k;
                    }
                    bd[k] = d; bi[k] = m;
                }
            }
        }
        int* o = &g_neigh[(size_t)(b * NN + r) * 4];
        o[0] = bi[0]; o[1] = bi[1]; o[2] = bi[2]; o[3] = bi[3];
    }
}

// ====== Kernel 1: n x n max-dot GEMM, 8x8 f32x2 tiles, padded smem ======
__global__ void __launch_bounds__(128)
main_kernel(const float* __restrict__ desc1, const float* __restrict__ desc2,
            float* __restrict__ out) {
    extern __shared__ __align__(16) char sm[];
    char* a_sm = sm;
    char* b_sm = sm + A_BYTES;
    float* vs  = reinterpret_cast<float*>(sm + A_BYTES + B_BYTES);
    __shared__ int s_last;
    __shared__ float rL[4], rM[4];

    int tid = threadIdx.x;
    int l = tid & 31, w = tid >> 5;
    int rt = (w << 2) | (l & 3);   // 0..15 -> rows rt*8..rt*8+7
    int ct = l >> 2;               // 0..7  -> cols ct*8..ct*8+7
    int chunk = blockIdx.x;        // 0..14
    int row0 = blockIdx.y * 128;
    int b = blockIdx.z;

    // ---- stage A tile once: 128 rows x 64 channels (padded chunks) ----
    {
        int grow = min(row0 + tid, NN - 1);
        char* dst = a_sm + (tid >> 3) * 80 + (tid & 7) * 8;
        const float* s1 = desc1 + (size_t)b * CC * NN + grow;
#pragma unroll
        for (int cp = 0; cp < 32; ++cp) {
            float x = s1[(size_t)(2 * cp) * NN];
            float y = s1[(size_t)(2 * cp + 1) * NN];
            *reinterpret_cast<float2*>(dst + cp * A_CP_STRIDE) = make_float2(x, y);
        }
    }

    // neighbor indices for my 8 rows (persist in regs)
    int4 nbq[8];
#pragma unroll
    for (int rr = 0; rr < 8; ++rr) {
        int grow = min(row0 + rt * 8 + rr, NN - 1);
        nbq[rr] = *reinterpret_cast<const int4*>(&g_neigh[(size_t)(b * NN + grow) * 4]);
    }

    float md[8];
#pragma unroll
    for (int rr = 0; rr < 8; ++rr) md[rr] = NEGBIG;

    int mycol0base = ct * 8;

    for (int t = 0; t < NTPC; ++t) {
        int colbase = (chunk * NTPC + t) * 64;
        // stage B tile: 64 cols x 64 channels
        {
            int col = tid & 63;
            int half = tid >> 6;   // 2 cps per pass
            char* dst = b_sm + (col >> 3) * 80 + (col & 7) * 8;
            const float* s2 = desc2 + (size_t)b * CC * NN + colbase + col;
#pragma unroll
            for (int k = 0; k < 16; ++k) {
                int cp = k * 2 + half;
                float x = s2[(size_t)(2 * cp) * NN];
                float y = s2[(size_t)(2 * cp + 1) * NN];
                *reinterpret_cast<float2*>(dst + cp * B_CP_STRIDE) = make_float2(x, y);
            }
            if (tid < 64) vs[tid] = g_visNeg[b * NN + colbase + tid];
        }
        __syncthreads();

        ull acc[64];
#pragma unroll
        for (int z = 0; z < 64; ++z) acc[z] = 0ull;

        const char* ap0 = a_sm + rt * 80;
        const char* bp0 = b_sm + ct * 80;
#pragma unroll 2
        for (int cp = 0; cp < 32; ++cp) {
            const char* ap = ap0 + cp * A_CP_STRIDE;
            const char* bp = bp0 + cp * B_CP_STRIDE;
            ulonglong2 a0 = *reinterpret_cast<const ulonglong2*>(ap);
            ulonglong2 a1 = *reinterpret_cast<const ulonglong2*>(ap + 16);
            ulonglong2 a2 = *reinterpret_cast<const ulonglong2*>(ap + 32);
            ulonglong2 a3 = *reinterpret_cast<const ulonglong2*>(ap + 48);
            ulonglong2 b0 = *reinterpret_cast<const ulonglong2*>(bp);
            ulonglong2 b1 = *reinterpret_cast<const ulonglong2*>(bp + 16);
            ulonglong2 b2 = *reinterpret_cast<const ulonglong2*>(bp + 32);
            ulonglong2 b3 = *reinterpret_cast<const ulonglong2*>(bp + 48);
            ull av[8] = {a0.x, a0.y, a1.x, a1.y, a2.x, a2.y, a3.x, a3.y};
            ull bv[8] = {b0.x, b0.y, b1.x, b1.y, b2.x, b2.y, b3.x, b3.y};
#pragma unroll
            for (int rr = 0; rr < 8; ++rr)
#pragma unroll
                for (int c = 0; c < 8; ++c)
                    ffma2(acc[rr * 8 + c], av[rr], bv[c]);
        }

        // epilogue: vis as additive -1e30 per col, neighbors via per-row bitmask
        float vneg[8];
#pragma unroll
        for (int c = 0; c < 8; ++c) vneg[c] = vs[mycol0base + c];
        int mycol0 = colbase + mycol0base;
#pragma unroll
        for (int rr = 0; rr < 8; ++rr) {
            unsigned mask = 0;
            int o0 = nbq[rr].x - mycol0; if ((unsigned)o0 < 8u) mask |= 1u << o0;
            int o1 = nbq[rr].y - mycol0; if ((unsigned)o1 < 8u) mask |= 1u << o1;
            int o2 = nbq[rr].z - mycol0; if ((unsigned)o2 < 8u) mask |= 1u << o2;
            int o3 = nbq[rr].w - mycol0; if ((unsigned)o3 < 8u) mask |= 1u << o3;
            float m = md[rr];
#pragma unroll
            for (int c = 0; c < 8; ++c) {
                float x, y; unpack2(acc[rr * 8 + c], x, y);
                float dot = x + y + vneg[c];
                if ((mask >> c) & 1u) dot = NEGBIG;
                m = fmaxf(m, dot);
            }
            md[rr] = m;
        }
        __syncthreads();
    }

    // reduce max over the 8 ct lanes (xor 4, 8, 16) and commit min
#pragma unroll
    for (int rr = 0; rr < 8; ++rr) {
        float m = md[rr];
#pragma unroll
        for (int off = 4; off <= 16; off <<= 1)
            m = fmaxf(m, __shfl_xor_sync(0xffffffffu, m, off));
        int grow = row0 + rt * 8 + rr;
        if (ct == 0 && grow < NN) {
            float neg = sqrtf(fmaxf(2.f - 2.f * m, EPSF));
            atomicMin(&g_negMinI[b * NN + grow], __float_as_int(neg));
        }
    }

    // ---- last block: deterministic final reduction ----
    __syncthreads();
    if (tid == 0) {
        __threadfence();
        s_last = (atomicAdd(&g_ctr, 1u) == TOTALB - 1) ? 1 : 0;
    }
    __syncthreads();
    if (s_last) {
        __threadfence();
        float aL = 0.f, aM = 0.f;
        for (int i = tid; i < BQ * NN; i += 128) {
            float neg = __int_as_float(g_negMinI[i]);
            float lv = fmaxf(g_posSim[i] - neg + 1.0f, 0.f);
            float mm = g_match[i];
            aL += lv * lv * mm;
            aM += mm;
        }
#pragma unroll
        for (int off = 16; off; off >>= 1) {
            aL += __shfl_xor_sync(0xffffffffu, aL, off);
            aM += __shfl_xor_sync(0xffffffffu, aM, off);
        }
        if (l == 0) { rL[w] = aL; rM[w] = aM; }
        __syncthreads();
        if (tid == 0) {
            float sL = 0.f, sM = 0.f;
#pragma unroll
            for (int q = 0; q < 4; ++q) { sL += rL[q]; sM += rM[q]; }
            out[0] = sL / sM;
        }
    }
}

// ---------------- launch ----------------
extern "C" void kernel_launch(void* const* d_in, const int* in_sizes, int n_in,
                              void* d_out, int out_size) {
    // metadata order: score1, score2, desc1, desc2, homo12, homo21
    const float* desc1  = (const float*)d_in[2];
    const float* desc2  = (const float*)d_in[3];
    const float* homo12 = (const float*)d_in[4];
    const float* homo21 = (const float*)d_in[5];

    cudaFuncSetAttribute(main_kernel, cudaFuncAttributeMaxDynamicSharedMemorySize,
                         SMEM_BYTES);
    prep_kernel<<<(BQ * NN + 7) / 8, 256>>>(desc1, desc2, homo12, homo21);
    dim3 g(NCH, ROWB, BQ);
    main_kernel<<<g, 128, SMEM_BYTES>>>(desc1, desc2, (float*)d_out);
}

// round 6
// speedup vs baseline: 3.0590x; 1.2232x over previous
#include <cuda_runtime.h>
#include <cuda_bf16.h>
#include <math.h>
#include <stdint.h>

// Problem constants (b=2, c=64, H=480, W=640, gs=8 -> hc=60, wc=80, n=4800)
#define BQ 2
#define CC 64
#define HC 60
#define WCC 80
#define NN 4800
#define HH 480
#define WW 640
#define EPSF 1e-8f
#define NEGBIG -1e30f
#define VISBIAS -30000.0f

// GEMM: M=N=4800 (pad 4864), K=192 bf16 (hi|lo|hi split + vis channel)
#define KK 192
#define NPAD 4864
#define MT 38                          // 38 tiles of 128
#define TOTALB (MT * MT * BQ)          // 2888
#define TILE_BYTES (128 * KK * 2)      // 49152
#define SMEM_BYTES (2 * TILE_BYTES + 128)

// ---------------- scratch (no allocations allowed) ----------------
__device__ float          g_visNeg[BQ * NN];
__device__ float          g_posSim[BQ * NN];
__device__ float          g_match[BQ * NN];
__device__ int            g_neigh[BQ * NN * 4];
__device__ int            g_negMinI[BQ * NN];
__device__ unsigned       g_ctr;
__device__ __nv_bfloat16  g_Asp[(size_t)BQ * NPAD * KK];
__device__ __nv_bfloat16  g_Bsp[(size_t)BQ * NPAD * KK];

__device__ __forceinline__ uint32_t smem_u32(const void* p) {
    uint32_t a;
    asm("{ .reg .u64 t; cvta.to.shared.u64 t, %1; cvt.u32.u64 %0, t; }"
        : "=r"(a) : "l"(p));
    return a;
}
__device__ __forceinline__ void ldsm4(uint32_t* r, uint32_t addr) {
    asm volatile("ldmatrix.sync.aligned.m8n8.x4.shared.b16 {%0,%1,%2,%3}, [%4];"
                 : "=r"(r[0]), "=r"(r[1]), "=r"(r[2]), "=r"(r[3]) : "r"(addr));
}
__device__ __forceinline__ void mma16816(float* c, const uint32_t* a,
                                         uint32_t b0, uint32_t b1) {
    asm volatile(
        "mma.sync.aligned.m16n8k16.row.col.f32.bf16.bf16.f32 "
        "{%0,%1,%2,%3}, {%4,%5,%6,%7}, {%8,%9}, {%0,%1,%2,%3};"
        : "+f"(c[0]), "+f"(c[1]), "+f"(c[2]), "+f"(c[3])
        : "r"(a[0]), "r"(a[1]), "r"(a[2]), "r"(a[3]), "r"(b0), "r"(b1));
}
__device__ __forceinline__ float inb_pix(float yi, float xi) {
    return (yi >= 0.f && yi <= (float)(HH - 1) && xi >= 0.f && xi <= (float)(WW - 1)) ? 1.f : 0.f;
}
__device__ __forceinline__ float inb_grid(float yi, float xi) {
    return (yi >= 0.f && yi <= (float)(HC - 1) && xi >= 0.f && xi <= (float)(WCC - 1)) ? 1.f : 0.f;
}

// ====== Kernel 0: per-row prep (warp per row): vis, 4-NN, posSim, match, init
__global__ void prep_kernel(const float* __restrict__ desc1,
                            const float* __restrict__ desc2,
                            const float* __restrict__ homo12,
                            const float* __restrict__ homo21) {
    if (blockIdx.x == 0 && threadIdx.x == 0) g_ctr = 0u;
    int w = blockIdx.x * 8 + (threadIdx.x >> 5);
    if (w >= BQ * NN) return;
    int lane = threadIdx.x & 31;
    int b = w / NN, r = w % NN;
    int iy = r / WCC, ix = r % WCC;

    {   // visibility of the 8x8 cell under homo21
        const float* h = homo21 + b * 9;
        float h0 = h[0], h1 = h[1], h2 = h[2], h3 = h[3], h4 = h[4],
              h5 = h[5], h6 = h[6], h7 = h[7], h8 = h[8];
        bool ok = true;
#pragma unroll
        for (int pp = 0; pp < 2; ++pp) {
            int p = lane + pp * 32;
            float x = (float)(ix * 8 + (p & 7));
            float y = (float)(iy * 8 + (p >> 3));
            float qx = h0 * x + h1 * y + h2;
            float qy = h3 * x + h4 * y + h5;
            float qz = h6 * x + h7 * y + h8;
            float wx = qx / (qz + EPSF);
            float wy = qy / (qz + EPSF);
            float y0 = floorf(wy), x0 = floorf(wx);
            float fy = wy - y0, fx = wx - x0;
            float val = (1.f - fy) * (1.f - fx) * inb_pix(y0, x0)
                      + (1.f - fy) * fx         * inb_pix(y0, x0 + 1.f)
                      + fy * (1.f - fx)         * inb_pix(y0 + 1.f, x0)
                      + fy * fx                 * inb_pix(y0 + 1.f, x0 + 1.f);
            ok = ok && (val > 0.f);
        }
        unsigned all = __all_sync(0xffffffffu, ok);
        if (lane == 0) {
            g_visNeg[b * NN + r] = all ? 0.f : NEGBIG;
            g_negMinI[b * NN + r] = 0x7F800000;
        }
    }

    const float* h = homo12 + b * 9;
    float px = (float)(ix * 8) + 3.5f;
    float py = (float)(iy * 8) + 3.5f;
    float qx = h[0] * px + h[1] * py + h[2];
    float qy = h[3] * px + h[4] * py + h[5];
    float qz = h[6] * px + h[7] * py + h[8];
    float wx = qx / (qz + EPSF);
    float wy = qy / (qz + EPSF);
    float dyc = (wy - 3.5f) * 0.125f;
    float dxc = (wx - 3.5f) * 0.125f;

    float y0 = floorf(dyc), x0 = floorf(dxc);
    float fy = dyc - y0, fx = dxc - x0;
    float e00 = (1.f - fy) * (1.f - fx) * inb_grid(y0, x0);
    float e01 = (1.f - fy) * fx         * inb_grid(y0, x0 + 1.f);
    float e10 = fy * (1.f - fx)         * inb_grid(y0 + 1.f, x0);
    float e11 = fy * fx                 * inb_grid(y0 + 1.f, x0 + 1.f);
    int yc0 = (int)fminf(fmaxf(y0, 0.f), (float)(HC - 1));
    int yc1 = (int)fminf(fmaxf(y0 + 1.f, 0.f), (float)(HC - 1));
    int xc0 = (int)fminf(fmaxf(x0, 0.f), (float)(WCC - 1));
    int xc1 = (int)fminf(fmaxf(x0 + 1.f, 0.f), (float)(WCC - 1));

    float sq = 0.f, dp = 0.f;
#pragma unroll
    for (int pp = 0; pp < 2; ++pp) {
        int ch = lane + 32 * pp;
        const float* base = desc2 + (size_t)(b * CC + ch) * NN;
        float v = e00 * base[yc0 * WCC + xc0] + e01 * base[yc0 * WCC + xc1]
                + e10 * base[yc1 * WCC + xc0] + e11 * base[yc1 * WCC + xc1];
        sq += v * v;
        dp += desc1[(size_t)(b * CC + ch) * NN + r] * v;
    }
#pragma unroll
    for (int off = 16; off; off >>= 1) {
        sq += __shfl_xor_sync(0xffffffffu, sq, off);
        dp += __shfl_xor_sync(0xffffffffu, dp, off);
    }

    if (lane == 0) {
        float posdot = dp / (sqrtf(sq) + EPSF);
        g_posSim[b * NN + r] = sqrtf(fmaxf(2.f - 2.f * posdot, EPSF));
        g_match[b * NN + r] =
            (wy >= 0.f && wy <= (float)(HH - 1) && wx >= 0.f && wx <= (float)(WW - 1)) ? 1.f : 0.f;

        float a2 = wy * wy + wx * wx;
        int xlo = (int)fminf(fmaxf(floorf(dxc) - 1.f, 0.f), (float)(WCC - 4));
        int ylo = (int)fminf(fmaxf(floorf(dyc) - 1.f, 0.f), (float)(HC - 4));
        float bd[4] = {1e30f, 1e30f, 1e30f, 1e30f};
        int bi[4] = {-1, -1, -1, -1};
#pragma unroll
        for (int jy = 0; jy < 4; ++jy) {
            int iyc = ylo + jy;
            float cy = (float)(iyc * 8) + 3.5f;
#pragma unroll
            for (int jx = 0; jx < 4; ++jx) {
                int ixc = xlo + jx;
                float cx = (float)(ixc * 8) + 3.5f;
                float d = sqrtf(fmaxf(a2 + cy * cy + cx * cx - 2.f * (wy * cy + wx * cx), 0.f));
                int m = iyc * WCC + ixc;
                if (d < bd[3]) {
                    int k = 3;
                    while (k > 0 && d < bd[k - 1]) {
                        bd[k] = bd[k - 1]; bi[k] = bi[k - 1]; --k;
                    }
                    bd[k] = d; bi[k] = m;
                }
            }
        }
        int* o = &g_neigh[(size_t)(b * NN + r) * 4];
        o[0] = bi[0]; o[1] = bi[1]; o[2] = bi[2]; o[3] = bi[3];
    }
}

// ====== Kernel 1: f32 -> split-bf16 scratch (A' and B' with vis channel) ======
__global__ void split_kernel(const float* __restrict__ desc1,
                             const float* __restrict__ desc2) {
    __shared__ float sd[CC][129];
    int b = blockIdx.y;
    int row0 = blockIdx.x * 128;
    int tid = threadIdx.x;   // 256 threads

    for (int i = tid; i < CC * 128; i += 256) {
        int ch = i >> 7, r = i & 127;
        int gr = row0 + r;
        sd[ch][r] = (gr < NN) ? desc1[(size_t)(b * CC + ch) * NN + gr] : 0.f;
    }
    __syncthreads();
    for (int i = tid; i < 128 * KK; i += 256) {
        int r = i / KK, k = i - r * KK;
        __nv_bfloat16 o;
        if (k < 64) {
            o = __float2bfloat16_rn(sd[k][r]);
        } else if (k < 128) {
            float v = sd[k - 64][r];
            __nv_bfloat16 hi = __float2bfloat16_rn(v);
            o = __float2bfloat16_rn(v - __bfloat162float(hi));
        } else if (k < 191) {
            o = __float2bfloat16_rn(sd[k - 128][r]);
        } else {
            o = __float2bfloat16_rn(1.0f);
        }
        g_Asp[((size_t)b * NPAD + row0 + r) * KK + k] = o;
    }
    __syncthreads();

    for (int i = tid; i < CC * 128; i += 256) {
        int ch = i >> 7, r = i & 127;
        int gr = row0 + r;
        sd[ch][r] = (gr < NN) ? desc2[(size_t)(b * CC + ch) * NN + gr] : 0.f;
    }
    __syncthreads();
    for (int i = tid; i < 128 * KK; i += 256) {
        int r = i / KK, k = i - r * KK;
        int gr = row0 + r;
        __nv_bfloat16 o;
        if (k < 64) {
            o = __float2bfloat16_rn(sd[k][r]);
        } else if (k < 128) {
            o = __float2bfloat16_rn(sd[k - 64][r]);
        } else if (k < 191) {
            float v = sd[k - 128][r];
            __nv_bfloat16 hi = __float2bfloat16_rn(v);
            o = __float2bfloat16_rn(v - __bfloat162float(hi));
        } else {
            float vb = (gr < NN && g_visNeg[b * NN + gr] == 0.f) ? 0.f : VISBIAS;
            o = __float2bfloat16_rn(vb);
        }
        g_Bsp[((size_t)b * NPAD + row0 + r) * KK + k] = o;
    }
}

// ====== Kernel 2: mma.sync bf16 GEMM + masked-max epilogue + final reduce ======
__global__ void __launch_bounds__(256, 2)
mma_kernel(float* __restrict__ out) {
    extern __shared__ char sm[];
    __shared__ int4  s_nb[128];      // neighbor cols rel to this ntile
    __shared__ float s_red[4][128];  // per-nwarp row maxima
    __shared__ int   s_last;
    __shared__ float rL[8], rM[8];

    int tid = threadIdx.x;
    int wid = tid >> 5, l = tid & 31;
    int wm = wid & 1, wn = wid >> 1;        // 2 x 4 warp grid
    int ntile = blockIdx.x, mtile = blockIdx.y, b = blockIdx.z;

    uint32_t dyn = smem_u32(sm);
    uint32_t au = (dyn + 127) & ~127u;
    char* a_ptr = sm + (au - dyn);
    char* b_ptr = a_ptr + TILE_BYTES;
    uint32_t bu = au + TILE_BYTES;

    if (tid < 128) {
        int grow = mtile * 128 + tid;
        int gr = grow < NN ? grow : NN - 1;
        int4 nb = *reinterpret_cast<const int4*>(&g_neigh[((size_t)b * NN + gr) * 4]);
        int cb = ntile * 128;
        nb.x -= cb; nb.y -= cb; nb.z -= cb; nb.w -= cb;
        s_nb[tid] = nb;
    }

    // stage A and B tiles, XOR-swizzled 16B chunks (24 chunks per 384B row)
    {
        const uint4* asrc = reinterpret_cast<const uint4*>(
            g_Asp + ((size_t)b * NPAD + mtile * 128) * KK);
        const uint4* bsrc = reinterpret_cast<const uint4*>(
            g_Bsp + ((size_t)b * NPAD + ntile * 128) * KK);
#pragma unroll
        for (int k = 0; k < 12; ++k) {
            int i = k * 256 + tid;
            int r = i / 24, c = i - r * 24;
            int pc = (c & 24) | ((c ^ (r & 7)) & 7);
            *reinterpret_cast<uint4*>(a_ptr + r * 384 + pc * 16) = asrc[i];
            *reinterpret_cast<uint4*>(b_ptr + r * 384 + pc * 16) = bsrc[i];
        }
    }
    __syncthreads();

    // per-lane ldmatrix addressing
    int lane7 = l & 7, mat = l >> 3, kh = mat >> 1;
    uint32_t aaddr[4], baddr[2];
#pragma unroll
    for (int mf = 0; mf < 4; ++mf)
        aaddr[mf] = au + (uint32_t)(wm * 64 + mf * 16 + (mat & 1) * 8 + lane7) * 384;
#pragma unroll
    for (int bf = 0; bf < 2; ++bf)
        baddr[bf] = bu + (uint32_t)(wn * 32 + bf * 16 + (mat & 1) * 8 + lane7) * 384;

    float cfr[4][4][4];
#pragma unroll
    for (int mf = 0; mf < 4; ++mf)
#pragma unroll
        for (int nf = 0; nf < 4; ++nf)
#pragma unroll
            for (int q = 0; q < 4; ++q) cfr[mf][nf][q] = 0.f;

#pragma unroll
    for (int ks = 0; ks < 12; ++ks) {
        int c16 = ks * 2 + kh;
        uint32_t pc = (uint32_t)(((c16 & 24) | ((c16 ^ lane7) & 7)) << 4);
        uint32_t af[4][4], bq[2][4];
#pragma unroll
        for (int mf = 0; mf < 4; ++mf) ldsm4(af[mf], aaddr[mf] + pc);
#pragma unroll
        for (int bf = 0; bf < 2; ++bf) ldsm4(bq[bf], baddr[bf] + pc);
#pragma unroll
        for (int mf = 0; mf < 4; ++mf)
#pragma unroll
            for (int nf = 0; nf < 4; ++nf)
                mma16816(cfr[mf][nf], af[mf],
                         bq[nf >> 1][nf & 1], bq[nf >> 1][2 + (nf & 1)]);
    }

    // epilogue: neighbor-masked max per row
#pragma unroll
    for (int mf = 0; mf < 4; ++mf) {
#pragma unroll
        for (int half = 0; half < 2; ++half) {
            int rl = wm * 64 + mf * 16 + (l >> 2) + half * 8;
            int4 nb = s_nb[rl];
            float mx = NEGBIG;
#pragma unroll
            for (int nf = 0; nf < 4; ++nf) {
                int c0 = wn * 32 + nf * 8 + (l & 3) * 2;
                int c1 = c0 + 1;
                float v0 = cfr[mf][nf][half * 2 + 0];
                float v1 = cfr[mf][nf][half * 2 + 1];
                bool m0 = (nb.x == c0) | (nb.y == c0) | (nb.z == c0) | (nb.w == c0);
                bool m1 = (nb.x == c1) | (nb.y == c1) | (nb.z == c1) | (nb.w == c1);
                mx = fmaxf(mx, m0 ? NEGBIG : v0);
                mx = fmaxf(mx, m1 ? NEGBIG : v1);
            }
            mx = fmaxf(mx, __shfl_xor_sync(0xffffffffu, mx, 1));
            mx = fmaxf(mx, __shfl_xor_sync(0xffffffffu, mx, 2));
            if ((l & 3) == 0) s_red[wn][rl] = mx;
        }
    }
    __syncthreads();
    if (tid < 128) {
        float m = fmaxf(fmaxf(s_red[0][tid], s_red[1][tid]),
                        fmaxf(s_red[2][tid], s_red[3][tid]));
        int grow = mtile * 128 + tid;
        if (grow < NN) {
            float neg = sqrtf(fmaxf(2.f - 2.f * m, EPSF));
            atomicMin(&g_negMinI[b * NN + grow], __float_as_int(neg));
        }
    }

    // last block: deterministic final reduction
    __syncthreads();
    if (tid == 0) {
        __threadfence();
        s_last = (atomicAdd(&g_ctr, 1u) == TOTALB - 1) ? 1 : 0;
    }
    __syncthreads();
    if (s_last) {
        __threadfence();
        float aL = 0.f, aM = 0.f;
        for (int i = tid; i < BQ * NN; i += 256) {
            float neg = __int_as_float(g_negMinI[i]);
            float lv = fmaxf(g_posSim[i] - neg + 1.0f, 0.f);
            float mm = g_match[i];
            aL += lv * lv * mm;
            aM += mm;
        }
#pragma unroll
        for (int off = 16; off; off >>= 1) {
            aL += __shfl_xor_sync(0xffffffffu, aL, off);
            aM += __shfl_xor_sync(0xffffffffu, aM, off);
        }
        if (l == 0) { rL[wid] = aL; rM[wid] = aM; }
        __syncthreads();
        if (tid == 0) {
            float sL = 0.f, sM = 0.f;
#pragma unroll
            for (int q = 0; q < 8; ++q) { sL += rL[q]; sM += rM[q]; }
            out[0] = sL / sM;
        }
    }
}

// ---------------- launch ----------------
extern "C" void kernel_launch(void* const* d_in, const int* in_sizes, int n_in,
                              void* d_out, int out_size) {
    // metadata order: score1, score2, desc1, desc2, homo12, homo21
    const float* desc1  = (const float*)d_in[2];
    const float* desc2  = (const float*)d_in[3];
    const float* homo12 = (const float*)d_in[4];
    const float* homo21 = (const float*)d_in[5];

    cudaFuncSetAttribute(mma_kernel, cudaFuncAttributeMaxDynamicSharedMemorySize,
                         SMEM_BYTES);
    prep_kernel<<<(BQ * NN + 7) / 8, 256>>>(desc1, desc2, homo12, homo21);
    split_kernel<<<dim3(MT, BQ), 256>>>(desc1, desc2);
    dim3 g(MT, MT, BQ);
    mma_kernel<<<g, 256, SMEM_BYTES>>>((float*)d_out);
}

// round 7
// speedup vs baseline: 4.3768x; 1.4308x over previous
#include <cuda_runtime.h>
#include <cuda_fp16.h>
#include <math.h>
#include <stdint.h>

// Problem constants (b=2, c=64, H=480, W=640, gs=8 -> hc=60, wc=80, n=4800)
#define BQ 2
#define CC 64
#define HC 60
#define WCC 80
#define NN 4800
#define HH 480
#define WW 640
#define EPSF 1e-8f
#define NEGBIG -1e30f

// GEMM: M=N=4800 (pad 4864), K=128 fp16 (hi|lo split), 128x128 tiles
#define KH 128
#define NPAD 4864
#define MT 38
#define TOTALB (MT * MT * BQ)          // 2888
#define ROWB 144                       // padded smem row stride (9 x 16B, odd)
#define CHUNK (128 * ROWB)             // 18432 bytes (one matrix, one k-chunk)
#define BUFSZ (2 * CHUNK)              // A + B for one k-chunk
#define SMEM_BYTES (2 * BUFSZ)         // double buffer: 73728

// ---------------- scratch (no allocations allowed) ----------------
__device__ float    g_visNeg[BQ * NN];     // 0 if visible else -1e30
__device__ float    g_posSim[BQ * NN];
__device__ float    g_match[BQ * NN];
__device__ int      g_neigh[BQ * NN * 4];
__device__ int      g_negMinI[BQ * NN];
__device__ unsigned g_ctr;
__device__ __align__(16) __half g_Ah[(size_t)BQ * NPAD * KH];
__device__ __align__(16) __half g_Bh[(size_t)BQ * NPAD * KH];

__device__ __forceinline__ uint32_t smem_u32(const void* p) {
    uint32_t a;
    asm("{ .reg .u64 t; cvta.to.shared.u64 t, %1; cvt.u32.u64 %0, t; }"
        : "=r"(a) : "l"(p));
    return a;
}
__device__ __forceinline__ void ldsm4(uint32_t* r, uint32_t addr) {
    asm volatile("ldmatrix.sync.aligned.m8n8.x4.shared.b16 {%0,%1,%2,%3}, [%4];"
                 : "=r"(r[0]), "=r"(r[1]), "=r"(r[2]), "=r"(r[3]) : "r"(addr));
}
__device__ __forceinline__ void mma16816(float* c, const uint32_t* a,
                                         uint32_t b0, uint32_t b1) {
    asm volatile(
        "mma.sync.aligned.m16n8k16.row.col.f32.f16.f16.f32 "
        "{%0,%1,%2,%3}, {%4,%5,%6,%7}, {%8,%9}, {%0,%1,%2,%3};"
        : "+f"(c[0]), "+f"(c[1]), "+f"(c[2]), "+f"(c[3])
        : "r"(a[0]), "r"(a[1]), "r"(a[2]), "r"(a[3]), "r"(b0), "r"(b1));
}
__device__ __forceinline__ void cp16(uint32_t dst, const void* src) {
    asm volatile("cp.async.cg.shared.global [%0], [%1], 16;"
                 :: "r"(dst), "l"(src) : "memory");
}
#define CP_COMMIT() asm volatile("cp.async.commit_group;" ::: "memory")
#define CP_WAIT(n)  asm volatile("cp.async.wait_group %0;" :: "n"(n) : "memory")

__device__ __forceinline__ float inb_grid(float yi, float xi) {
    return (yi >= 0.f && yi <= (float)(HC - 1) && xi >= 0.f && xi <= (float)(WCC - 1)) ? 1.f : 0.f;
}

// ====== Kernel 0: per-row prep: vis (arithmetic), 4-NN (parallel), posSim ====
__global__ void prep_kernel(const float* __restrict__ desc1,
                            const float* __restrict__ desc2,
                            const float* __restrict__ homo12,
                            const float* __restrict__ homo21) {
    if (blockIdx.x == 0 && threadIdx.x == 0) g_ctr = 0u;
    int w = blockIdx.x * 8 + (threadIdx.x >> 5);
    if (w >= BQ * NN) return;
    int lane = threadIdx.x & 31;
    int b = w / NN, r = w % NN;
    int iy = r / WCC, ix = r % WCC;

    // ---- visibility: bilinear(ones) > 0  <=>  wy in (-1,H) and wx in (-1,W)
    {
        const float* h = homo21 + b * 9;
        float h0 = h[0], h1 = h[1], h2 = h[2], h3 = h[3], h4 = h[4],
              h5 = h[5], h6 = h[6], h7 = h[7], h8 = h[8];
        bool ok = true;
#pragma unroll
        for (int pp = 0; pp < 2; ++pp) {
            int p = lane + pp * 32;
            float x = (float)(ix * 8 + (p & 7));
            float y = (float)(iy * 8 + (p >> 3));
            float qx = h0 * x + h1 * y + h2;
            float qy = h3 * x + h4 * y + h5;
            float qz = h6 * x + h7 * y + h8;
            float wx = qx / (qz + EPSF);
            float wy = qy / (qz + EPSF);
            ok = ok && (wy > -1.f) && (wy < (float)HH)
                    && (wx > -1.f) && (wx < (float)WW);
        }
        unsigned all = __all_sync(0xffffffffu, ok);
        if (lane == 0) {
            g_visNeg[b * NN + r] = all ? 0.f : NEGBIG;
            g_negMinI[b * NN + r] = 0x7F800000;
        }
    }

    // ---- warp point under homo12 (uniform across warp) ----
    const float* h = homo12 + b * 9;
    float px = (float)(ix * 8) + 3.5f;
    float py = (float)(iy * 8) + 3.5f;
    float qx = h[0] * px + h[1] * py + h[2];
    float qy = h[3] * px + h[4] * py + h[5];
    float qz = h[6] * px + h[7] * py + h[8];
    float wx = qx / (qz + EPSF);
    float wy = qy / (qz + EPSF);
    float dyc = (wy - 3.5f) * 0.125f;
    float dxc = (wx - 3.5f) * 0.125f;

    // ---- 4-NN across lanes 0..15 (4x4 clamped window), tie -> lower index ----
    int bi4[4];
    {
        int xlo = (int)fminf(fmaxf(floorf(dxc) - 1.f, 0.f), (float)(WCC - 4));
        int ylo = (int)fminf(fmaxf(floorf(dyc) - 1.f, 0.f), (float)(HC - 4));
        unsigned long long pk = ~0ull;
        if (lane < 16) {
            int iyc = ylo + (lane >> 2);
            int ixc = xlo + (lane & 3);
            float cy = (float)(iyc * 8) + 3.5f;
            float cx = (float)(ixc * 8) + 3.5f;
            float a2 = wy * wy + wx * wx;
            float d2 = fmaxf(a2 + cy * cy + cx * cx - 2.f * (wy * cy + wx * cx), 0.f);
            int m = iyc * WCC + ixc;
            pk = ((unsigned long long)__float_as_uint(d2) << 32) | (unsigned)m;
        }
#pragma unroll
        for (int k = 0; k < 4; ++k) {
            unsigned long long red = pk;
#pragma unroll
            for (int off = 16; off; off >>= 1)
                red = min(red, __shfl_xor_sync(0xffffffffu, red, off));
            bi4[k] = (int)(red & 0xffffffffu);
            if (pk == red) pk = ~0ull;
        }
    }

    // ---- bilinear w_desc1, pos_sim (2 channels per lane) ----
    float y0 = floorf(dyc), x0 = floorf(dxc);
    float fy = dyc - y0, fx = dxc - x0;
    float e00 = (1.f - fy) * (1.f - fx) * inb_grid(y0, x0);
    float e01 = (1.f - fy) * fx         * inb_grid(y0, x0 + 1.f);
    float e10 = fy * (1.f - fx)         * inb_grid(y0 + 1.f, x0);
    float e11 = fy * fx                 * inb_grid(y0 + 1.f, x0 + 1.f);
    int yc0 = (int)fminf(fmaxf(y0, 0.f), (float)(HC - 1));
    int yc1 = (int)fminf(fmaxf(y0 + 1.f, 0.f), (float)(HC - 1));
    int xc0 = (int)fminf(fmaxf(x0, 0.f), (float)(WCC - 1));
    int xc1 = (int)fminf(fmaxf(x0 + 1.f, 0.f), (float)(WCC - 1));

    float sq = 0.f, dp = 0.f;
#pragma unroll
    for (int pp = 0; pp < 2; ++pp) {
        int ch = lane + 32 * pp;
        const float* base = desc2 + (size_t)(b * CC + ch) * NN;
        float v = e00 * base[yc0 * WCC + xc0] + e01 * base[yc0 * WCC + xc1]
                + e10 * base[yc1 * WCC + xc0] + e11 * base[yc1 * WCC + xc1];
        sq += v * v;
        dp += desc1[(size_t)(b * CC + ch) * NN + r] * v;
    }
#pragma unroll
    for (int off = 16; off; off >>= 1) {
        sq += __shfl_xor_sync(0xffffffffu, sq, off);
        dp += __shfl_xor_sync(0xffffffffu, dp, off);
    }

    if (lane == 0) {
        float posdot = dp / (sqrtf(sq) + EPSF);
        g_posSim[b * NN + r] = sqrtf(fmaxf(2.f - 2.f * posdot, EPSF));
        g_match[b * NN + r] =
            (wy >= 0.f && wy <= (float)(HH - 1) && wx >= 0.f && wx <= (float)(WW - 1)) ? 1.f : 0.f;
        int* o = &g_neigh[(size_t)(b * NN + r) * 4];
        o[0] = bi4[0]; o[1] = bi4[1]; o[2] = bi4[2]; o[3] = bi4[3];
    }
}

// ====== Kernel 1: f32 -> fp16 hi|lo split scratch (K = 64 hi + 64 lo) ======
__global__ void split_kernel(const float* __restrict__ desc1,
                             const float* __restrict__ desc2) {
    __shared__ float sd[CC][129];
    int b = blockIdx.y;
    int row0 = blockIdx.x * 128;
    int tid = threadIdx.x;   // 256 threads

    for (int i = tid; i < CC * 128; i += 256) {
        int ch = i >> 7, r = i & 127;
        int gr = row0 + r;
        sd[ch][r] = (gr < NN) ? desc1[(size_t)(b * CC + ch) * NN + gr] : 0.f;
    }
    __syncthreads();
    for (int i = tid; i < 128 * KH; i += 256) {
        int r = i >> 7, k = i & 127;
        float v = sd[k & 63][r];
        __half hi = __float2half_rn(v);
        __half o = (k < 64) ? hi : __float2half_rn(v - __half2float(hi));
        g_Ah[((size_t)b * NPAD + row0 + r) * KH + k] = o;
    }
    __syncthreads();

    for (int i = tid; i < CC * 128; i += 256) {
        int ch = i >> 7, r = i & 127;
        int gr = row0 + r;
        sd[ch][r] = (gr < NN) ? desc2[(size_t)(b * CC + ch) * NN + gr] : 0.f;
    }
    __syncthreads();
    for (int i = tid; i < 128 * KH; i += 256) {
        int r = i >> 7, k = i & 127;
        float v = sd[k & 63][r];
        __half hi = __float2half_rn(v);
        __half o = (k < 64) ? hi : __float2half_rn(v - __half2float(hi));
        g_Bh[((size_t)b * NPAD + row0 + r) * KH + k] = o;
    }
}

// ====== Kernel 2: pipelined fp16 GEMM + masked-max epilogue + final reduce ===
__global__ void __launch_bounds__(256, 2)
mma_kernel(float* __restrict__ out) {
    extern __shared__ char sm[];
    __shared__ int4  s_nb[128];
    __shared__ float s_vs[128];
    __shared__ float s_red[4][128];
    __shared__ int   s_last;
    __shared__ float rL[8], rM[8];

    int tid = threadIdx.x;
    int wid = tid >> 5, l = tid & 31;
    int wm = wid & 1, wn = wid >> 1;
    int ntile = blockIdx.x, mtile = blockIdx.y, b = blockIdx.z;

    uint32_t au = smem_u32(sm);

    const __half* Asrc = g_Ah + ((size_t)b * NPAD + mtile * 128) * KH;
    const __half* Bsrc = g_Bh + ((size_t)b * NPAD + ntile * 128) * KH;

    // prologue: issue both k-chunks via cp.async (chunk c -> buffer c)
#pragma unroll
    for (int c = 0; c < 2; ++c) {
        uint32_t sb = au + c * BUFSZ;
#pragma unroll
        for (int t = 0; t < 4; ++t) {
            int i = t * 256 + tid, r = i >> 3, g = i & 7;
            cp16(sb + r * ROWB + g * 16, Asrc + (size_t)r * KH + c * 64 + g * 8);
        }
#pragma unroll
        for (int t = 0; t < 4; ++t) {
            int i = t * 256 + tid, r = i >> 3, g = i & 7;
            cp16(sb + CHUNK + r * ROWB + g * 16, Bsrc + (size_t)r * KH + c * 64 + g * 8);
        }
        CP_COMMIT();
    }

    // stage neighbor indices + vis while loads fly
    if (tid < 128) {
        int grow = mtile * 128 + tid;
        int gr = grow < NN ? grow : NN - 1;
        int4 nb = *reinterpret_cast<const int4*>(&g_neigh[((size_t)b * NN + gr) * 4]);
        int cb = ntile * 128;
        nb.x -= cb; nb.y -= cb; nb.z -= cb; nb.w -= cb;
        s_nb[tid] = nb;
        int gcol = ntile * 128 + tid;
        s_vs[tid] = (gcol < NN) ? g_visNeg[b * NN + gcol] : NEGBIG;
    }

    // ldmatrix per-lane row offsets
    int lane7 = l & 7, mat = l >> 3, kh = mat >> 1;
    uint32_t arow[4], brow[2];
#pragma unroll
    for (int mf = 0; mf < 4; ++mf)
        arow[mf] = (uint32_t)(wm * 64 + mf * 16 + (mat & 1) * 8 + lane7) * ROWB;
#pragma unroll
    for (int bf = 0; bf < 2; ++bf)
        brow[bf] = (uint32_t)(wn * 32 + bf * 16 + (mat & 1) * 8 + lane7) * ROWB + CHUNK;

    float cfr[4][4][4];
#pragma unroll
    for (int mf = 0; mf < 4; ++mf)
#pragma unroll
        for (int nf = 0; nf < 4; ++nf)
#pragma unroll
            for (int q = 0; q < 4; ++q) cfr[mf][nf][q] = 0.f;

    // chunk 0: wait first group only (chunk 1 still in flight)
    CP_WAIT(1);
    __syncthreads();
#pragma unroll
    for (int c = 0; c < 2; ++c) {
        uint32_t base = au + c * BUFSZ;
#pragma unroll
        for (int ks = 0; ks < 4; ++ks) {
            uint32_t g16 = (uint32_t)((ks * 2 + kh) << 4);
            uint32_t af[4][4], bq[2][4];
#pragma unroll
            for (int mf = 0; mf < 4; ++mf) ldsm4(af[mf], base + arow[mf] + g16);
#pragma unroll
            for (int bf = 0; bf < 2; ++bf) ldsm4(bq[bf], base + brow[bf] + g16);
#pragma unroll
            for (int mf = 0; mf < 4; ++mf)
#pragma unroll
                for (int nf = 0; nf < 4; ++nf)
                    mma16816(cfr[mf][nf], af[mf],
                             bq[nf >> 1][nf & 1], bq[nf >> 1][2 + (nf & 1)]);
        }
        if (c == 0) {
            CP_WAIT(0);
            __syncthreads();
        }
    }

    // epilogue: vis add + neighbor-masked max per row
#pragma unroll
    for (int mf = 0; mf < 4; ++mf) {
#pragma unroll
        for (int half = 0; half < 2; ++half) {
            int rl = wm * 64 + mf * 16 + (l >> 2) + half * 8;
            int4 nb = s_nb[rl];
            float mx = NEGBIG;
#pragma unroll
            for (int nf = 0; nf < 4; ++nf) {
                int c0 = wn * 32 + nf * 8 + (l & 3) * 2;
                int c1 = c0 + 1;
                float v0 = cfr[mf][nf][half * 2 + 0] + s_vs[c0];
                float v1 = cfr[mf][nf][half * 2 + 1] + s_vs[c1];
                bool m0 = (nb.x == c0) | (nb.y == c0) | (nb.z == c0) | (nb.w == c0);
                bool m1 = (nb.x == c1) | (nb.y == c1) | (nb.z == c1) | (nb.w == c1);
                mx = fmaxf(mx, m0 ? NEGBIG : v0);
                mx = fmaxf(mx, m1 ? NEGBIG : v1);
            }
            mx = fmaxf(mx, __shfl_xor_sync(0xffffffffu, mx, 1));
            mx = fmaxf(mx, __shfl_xor_sync(0xffffffffu, mx, 2));
            if ((l & 3) == 0) s_red[wn][rl] = mx;
        }
    }
    __syncthreads();
    if (tid < 128) {
        float m = fmaxf(fmaxf(s_red[0][tid], s_red[1][tid]),
                        fmaxf(s_red[2][tid], s_red[3][tid]));
        int grow = mtile * 128 + tid;
        if (grow < NN) {
            float neg = sqrtf(fmaxf(2.f - 2.f * m, EPSF));
            atomicMin(&g_negMinI[b * NN + grow], __float_as_int(neg));
        }
    }

    // last block: deterministic final reduction
    __syncthreads();
    if (tid == 0) {
        __threadfence();
        s_last = (atomicAdd(&g_ctr, 1u) == TOTALB - 1) ? 1 : 0;
    }
    __syncthreads();
    if (s_last) {
        __threadfence();
        float aL = 0.f, aM = 0.f;
        for (int i = tid; i < BQ * NN; i += 256) {
            float neg = __int_as_float(g_negMinI[i]);
            float lv = fmaxf(g_posSim[i] - neg + 1.0f, 0.f);
            float mm = g_match[i];
            aL += lv * lv * mm;
            aM += mm;
        }
#pragma unroll
        for (int off = 16; off; off >>= 1) {
            aL += __shfl_xor_sync(0xffffffffu, aL, off);
            aM += __shfl_xor_sync(0xffffffffu, aM, off);
        }
        if (l == 0) { rL[wid] = aL; rM[wid] = aM; }
        __syncthreads();
        if (tid == 0) {
            float sL = 0.f, sM = 0.f;
#pragma unroll
            for (int q = 0; q < 8; ++q) { sL += rL[q]; sM += rM[q]; }
            out[0] = sL / sM;
        }
    }
}

// ---------------- launch ----------------
extern "C" void kernel_launch(void* const* d_in, const int* in_sizes, int n_in,
                              void* d_out, int out_size) {
    // metadata order: score1, score2, desc1, desc2, homo12, homo21
    const float* desc1  = (const float*)d_in[2];
    const float* desc2  = (const float*)d_in[3];
    const float* homo12 = (const float*)d_in[4];
    const float* homo21 = (const float*)d_in[5];

    cudaFuncSetAttribute(mma_kernel, cudaFuncAttributeMaxDynamicSharedMemorySize,
                         SMEM_BYTES);
    prep_kernel<<<(BQ * NN + 7) / 8, 256>>>(desc1, desc2, homo12, homo21);
    split_kernel<<<dim3(MT, BQ), 256>>>(desc1, desc2);
    dim3 g(MT, MT, BQ);
    mma_kernel<<<g, 256, SMEM_BYTES>>>((float*)d_out);
}

// round 8
// speedup vs baseline: 4.3978x; 1.0048x over previous
#include <cuda_runtime.h>
#include <cuda_fp16.h>
#include <math.h>
#include <stdint.h>

// Problem constants (b=2, c=64, H=480, W=640, gs=8 -> hc=60, wc=80, n=4800)
#define BQ 2
#define CC 64
#define HC 60
#define WCC 80
#define NN 4800
#define HH 480
#define WW 640
#define EPSF 1e-8f
#define NEGBIG -1e30f

// GEMM: M=N=4800 (pad 4864), K=128 fp16 (hi|lo split), 128x128 tiles
#define KH 128
#define NPAD 4864
#define MT 38
#define TOTALB (MT * MT * BQ)          // 2888
#define ROWB 272                       // 17 x 16B, odd multiple -> conflict-free
#define CHUNK (128 * ROWB)             // 34816 bytes per matrix tile
#define SMEM_BYTES (2 * CHUNK)         // 69632

// ---------------- scratch (no allocations allowed) ----------------
__device__ float    g_visNeg[BQ * NN];     // 0 if visible else -1e30
__device__ float    g_posSim[BQ * NN];
__device__ float    g_match[BQ * NN];
__device__ int      g_neigh[BQ * NN * 4];
__device__ int      g_negMinI[BQ * NN];
__device__ unsigned g_ctr;
__device__ __align__(16) __half g_Ah[(size_t)BQ * NPAD * KH];
__device__ __align__(16) __half g_Bh[(size_t)BQ * NPAD * KH];

__device__ __forceinline__ uint32_t smem_u32(const void* p) {
    uint32_t a;
    asm("{ .reg .u64 t; cvta.to.shared.u64 t, %1; cvt.u32.u64 %0, t; }"
        : "=r"(a) : "l"(p));
    return a;
}
__device__ __forceinline__ void ldsm4(uint32_t* r, uint32_t addr) {
    asm volatile("ldmatrix.sync.aligned.m8n8.x4.shared.b16 {%0,%1,%2,%3}, [%4];"
                 : "=r"(r[0]), "=r"(r[1]), "=r"(r[2]), "=r"(r[3]) : "r"(addr));
}
__device__ __forceinline__ void mma16816(float* c, const uint32_t* a,
                                         uint32_t b0, uint32_t b1) {
    asm volatile(
        "mma.sync.aligned.m16n8k16.row.col.f32.f16.f16.f32 "
        "{%0,%1,%2,%3}, {%4,%5,%6,%7}, {%8,%9}, {%0,%1,%2,%3};"
        : "+f"(c[0]), "+f"(c[1]), "+f"(c[2]), "+f"(c[3])
        : "r"(a[0]), "r"(a[1]), "r"(a[2]), "r"(a[3]), "r"(b0), "r"(b1));
}
__device__ __forceinline__ void cp16(uint32_t dst, const void* src) {
    asm volatile("cp.async.cg.shared.global [%0], [%1], 16;"
                 :: "r"(dst), "l"(src) : "memory");
}
#define CP_COMMIT() asm volatile("cp.async.commit_group;" ::: "memory")
#define CP_WAIT(n)  asm volatile("cp.async.wait_group %0;" :: "n"(n) : "memory")

__device__ __forceinline__ float inb_grid(float yi, float xi) {
    return (yi >= 0.f && yi <= (float)(HC - 1) && xi >= 0.f && xi <= (float)(WCC - 1)) ? 1.f : 0.f;
}

// ====== Kernel 0: per-row prep, THREAD per row (coalesced gathers) ======
__global__ void prep_kernel(const float* __restrict__ desc1,
                            const float* __restrict__ desc2,
                            const float* __restrict__ homo12,
                            const float* __restrict__ homo21) {
    int t = blockIdx.x * 256 + threadIdx.x;
    if (t == 0) g_ctr = 0u;
    if (t >= BQ * NN) return;
    int b = t / NN, r = t % NN;
    int iy = r / WCC, ix = r % WCC;

    // ---- visibility: all 64 cell pixels, division-free sign tests ----
    {
        const float* h = homo21 + b * 9;
        float h0 = h[0], h1 = h[1], h2 = h[2], h3 = h[3], h4 = h[4],
              h5 = h[5], h6 = h[6], h7 = h[7], h8 = h[8];
        float cx0 = (float)(ix * 8), cy0 = (float)(iy * 8);
        bool ok = true;
#pragma unroll
        for (int dy = 0; dy < 8; ++dy) {
            float y = cy0 + (float)dy;
            float qxr = h0 * cx0 + h1 * y + h2;
            float qyr = h3 * cx0 + h4 * y + h5;
            float qzr = h6 * cx0 + h7 * y + h8;
#pragma unroll
            for (int dx = 0; dx < 8; ++dx) {
                float qx = qxr + h0 * (float)dx;
                float qy = qyr + h3 * (float)dx;
                float z  = qzr + h6 * (float)dx + EPSF;
                // wy > -1, wy < H, wx > -1, wx < W  (sign-safe in z)
                ok = ok && ((qy + z) * z > 0.f)
                        && (((float)HH * z - qy) * z > 0.f)
                        && ((qx + z) * z > 0.f)
                        && (((float)WW * z - qx) * z > 0.f);
            }
        }
        g_visNeg[t] = ok ? 0.f : NEGBIG;
        g_negMinI[t] = 0x7F800000;
    }

    // ---- warp point under homo12 ----
    const float* h = homo12 + b * 9;
    float px = (float)(ix * 8) + 3.5f;
    float py = (float)(iy * 8) + 3.5f;
    float qx = h[0] * px + h[1] * py + h[2];
    float qy = h[3] * px + h[4] * py + h[5];
    float qz = h[6] * px + h[7] * py + h[8];
    float wx = qx / (qz + EPSF);
    float wy = qy / (qz + EPSF);
    float dyc = (wy - 3.5f) * 0.125f;
    float dxc = (wx - 3.5f) * 0.125f;

    // ---- 4-NN in clamped 4x4 window (tie -> lower index) ----
    {
        float a2 = wy * wy + wx * wx;
        int xlo = (int)fminf(fmaxf(floorf(dxc) - 1.f, 0.f), (float)(WCC - 4));
        int ylo = (int)fminf(fmaxf(floorf(dyc) - 1.f, 0.f), (float)(HC - 4));
        float bd[4] = {1e30f, 1e30f, 1e30f, 1e30f};
        int bi[4] = {-1, -1, -1, -1};
#pragma unroll
        for (int jy = 0; jy < 4; ++jy) {
            int iyc = ylo + jy;
            float cy = (float)(iyc * 8) + 3.5f;
#pragma unroll
            for (int jx = 0; jx < 4; ++jx) {
                int ixc = xlo + jx;
                float cx = (float)(ixc * 8) + 3.5f;
                float d = a2 + cy * cy + cx * cx - 2.f * (wy * cy + wx * cx);
                int m = iyc * WCC + ixc;
                if (d < bd[3]) {
                    int k = 3;
                    while (k > 0 && d < bd[k - 1]) {
                        bd[k] = bd[k - 1]; bi[k] = bi[k - 1]; --k;
                    }
                    bd[k] = d; bi[k] = m;
                }
            }
        }
        int* o = &g_neigh[(size_t)t * 4];
        o[0] = bi[0]; o[1] = bi[1]; o[2] = bi[2]; o[3] = bi[3];
    }

    // ---- bilinear w_desc1 + pos_sim: channel loop, coalesced across lanes ----
    float y0 = floorf(dyc), x0 = floorf(dxc);
    float fy = dyc - y0, fx = dxc - x0;
    float e00 = (1.f - fy) * (1.f - fx) * inb_grid(y0, x0);
    float e01 = (1.f - fy) * fx         * inb_grid(y0, x0 + 1.f);
    float e10 = fy * (1.f - fx)         * inb_grid(y0 + 1.f, x0);
    float e11 = fy * fx                 * inb_grid(y0 + 1.f, x0 + 1.f);
    int yc0 = (int)fminf(fmaxf(y0, 0.f), (float)(HC - 1));
    int yc1 = (int)fminf(fmaxf(y0 + 1.f, 0.f), (float)(HC - 1));
    int xc0 = (int)fminf(fmaxf(x0, 0.f), (float)(WCC - 1));
    int xc1 = (int)fminf(fmaxf(x0 + 1.f, 0.f), (float)(WCC - 1));
    int c00 = yc0 * WCC + xc0, c01 = yc0 * WCC + xc1;
    int c10 = yc1 * WCC + xc0, c11 = yc1 * WCC + xc1;

    const float* d2b = desc2 + (size_t)b * CC * NN;
    const float* d1b = desc1 + (size_t)b * CC * NN + r;
    float sq = 0.f, dp = 0.f;
#pragma unroll 4
    for (int ch = 0; ch < CC; ++ch) {
        const float* p = d2b + (size_t)ch * NN;
        float v = e00 * p[c00] + e01 * p[c01] + e10 * p[c10] + e11 * p[c11];
        sq += v * v;
        dp += d1b[(size_t)ch * NN] * v;
    }
    float posdot = dp / (sqrtf(sq) + EPSF);
    g_posSim[t] = sqrtf(fmaxf(2.f - 2.f * posdot, EPSF));
    g_match[t] =
        (wy >= 0.f && wy <= (float)(HH - 1) && wx >= 0.f && wx <= (float)(WW - 1)) ? 1.f : 0.f;
}

// ====== Kernel 1: f32 -> fp16 hi|lo split scratch (K = 64 hi + 64 lo) ======
__global__ void split_kernel(const float* __restrict__ desc1,
                             const float* __restrict__ desc2) {
    __shared__ float sd[CC][129];
    int b = blockIdx.y;
    int row0 = blockIdx.x * 128;
    int tid = threadIdx.x;   // 256 threads

    for (int i = tid; i < CC * 128; i += 256) {
        int ch = i >> 7, r = i & 127;
        int gr = row0 + r;
        sd[ch][r] = (gr < NN) ? desc1[(size_t)(b * CC + ch) * NN + gr] : 0.f;
    }
    __syncthreads();
    for (int i = tid; i < 128 * KH; i += 256) {
        int r = i >> 7, k = i & 127;
        float v = sd[k & 63][r];
        __half hi = __float2half_rn(v);
        __half o = (k < 64) ? hi : __float2half_rn(v - __half2float(hi));
        g_Ah[((size_t)b * NPAD + row0 + r) * KH + k] = o;
    }
    __syncthreads();

    for (int i = tid; i < CC * 128; i += 256) {
        int ch = i >> 7, r = i & 127;
        int gr = row0 + r;
        sd[ch][r] = (gr < NN) ? desc2[(size_t)(b * CC + ch) * NN + gr] : 0.f;
    }
    __syncthreads();
    for (int i = tid; i < 128 * KH; i += 256) {
        int r = i >> 7, k = i & 127;
        float v = sd[k & 63][r];
        __half hi = __float2half_rn(v);
        __half o = (k < 64) ? hi : __float2half_rn(v - __half2float(hi));
        g_Bh[((size_t)b * NPAD + row0 + r) * KH + k] = o;
    }
}

// ====== Kernel 2: fp16 GEMM, 4 warps, 64x64 warp tiles + epilogue ======
__global__ void __launch_bounds__(128, 2)
mma_kernel(float* __restrict__ out) {
    extern __shared__ char sm[];
    __shared__ int4  s_nb[128];
    __shared__ float s_vs[128];
    __shared__ float s_red[2][128];
    __shared__ int   s_last;
    __shared__ float rL[4], rM[4];

    int tid = threadIdx.x;
    int wid = tid >> 5, l = tid & 31;
    int wm = wid & 1, wn = wid >> 1;        // 2 x 2 warp grid
    int ntile = blockIdx.x, mtile = blockIdx.y, b = blockIdx.z;

    uint32_t au = smem_u32(sm);
    const __half* Asrc = g_Ah + ((size_t)b * NPAD + mtile * 128) * KH;
    const __half* Bsrc = g_Bh + ((size_t)b * NPAD + ntile * 128) * KH;

    // full-K tiles via cp.async: 16 x 16B chunks per thread per matrix
#pragma unroll
    for (int tq = 0; tq < 16; ++tq) {
        int i = tq * 128 + tid, rr = i >> 4, g = i & 15;
        cp16(au + rr * ROWB + g * 16, Asrc + (size_t)rr * KH + g * 8);
    }
#pragma unroll
    for (int tq = 0; tq < 16; ++tq) {
        int i = tq * 128 + tid, rr = i >> 4, g = i & 15;
        cp16(au + CHUNK + rr * ROWB + g * 16, Bsrc + (size_t)rr * KH + g * 8);
    }
    CP_COMMIT();

    // stage neighbor indices + vis while loads fly
    {
        int grow = mtile * 128 + tid;
        int gr = grow < NN ? grow : NN - 1;
        int4 nb = *reinterpret_cast<const int4*>(&g_neigh[((size_t)b * NN + gr) * 4]);
        int cb = ntile * 128;
        nb.x -= cb; nb.y -= cb; nb.z -= cb; nb.w -= cb;
        s_nb[tid] = nb;
        int gcol = ntile * 128 + tid;
        s_vs[tid] = (gcol < NN) ? g_visNeg[b * NN + gcol] : NEGBIG;
    }

    // ldmatrix per-lane row offsets (warp tile 64x64)
    int lane7 = l & 7, mat = l >> 3, kh = mat >> 1;
    uint32_t arow[4], brow[4];
#pragma unroll
    for (int mf = 0; mf < 4; ++mf)
        arow[mf] = (uint32_t)(wm * 64 + mf * 16 + (mat & 1) * 8 + lane7) * ROWB;
#pragma unroll
    for (int bf = 0; bf < 4; ++bf)
        brow[bf] = (uint32_t)(wn * 64 + bf * 16 + (mat & 1) * 8 + lane7) * ROWB + CHUNK;

    float cfr[4][8][4];
#pragma unroll
    for (int mf = 0; mf < 4; ++mf)
#pragma unroll
        for (int nf = 0; nf < 8; ++nf)
#pragma unroll
            for (int q = 0; q < 4; ++q) cfr[mf][nf][q] = 0.f;

    CP_WAIT(0);
    __syncthreads();

#pragma unroll
    for (int ks = 0; ks < 8; ++ks) {
        uint32_t g16 = (uint32_t)((ks * 2 + kh) << 4);
        uint32_t af[4][4], bq[4][4];
#pragma unroll
        for (int mf = 0; mf < 4; ++mf) ldsm4(af[mf], au + arow[mf] + g16);
#pragma unroll
        for (int bf = 0; bf < 4; ++bf) ldsm4(bq[bf], au + brow[bf] + g16);
#pragma unroll
        for (int mf = 0; mf < 4; ++mf)
#pragma unroll
            for (int nf = 0; nf < 8; ++nf)
                mma16816(cfr[mf][nf], af[mf],
                         bq[nf >> 1][nf & 1], bq[nf >> 1][2 + (nf & 1)]);
    }

    // epilogue: vis add + neighbor-masked max per row
#pragma unroll
    for (int mf = 0; mf < 4; ++mf) {
#pragma unroll
        for (int half = 0; half < 2; ++half) {
            int rl = wm * 64 + mf * 16 + (l >> 2) + half * 8;
            int4 nb = s_nb[rl];
            float mx = NEGBIG;
#pragma unroll
            for (int nf = 0; nf < 8; ++nf) {
                int c0 = wn * 64 + nf * 8 + (l & 3) * 2;
                int c1 = c0 + 1;
                float v0 = cfr[mf][nf][half * 2 + 0] + s_vs[c0];
                float v1 = cfr[mf][nf][half * 2 + 1] + s_vs[c1];
                bool m0 = (nb.x == c0) | (nb.y == c0) | (nb.z == c0) | (nb.w == c0);
                bool m1 = (nb.x == c1) | (nb.y == c1) | (nb.z == c1) | (nb.w == c1);
                mx = fmaxf(mx, m0 ? NEGBIG : v0);
                mx = fmaxf(mx, m1 ? NEGBIG : v1);
            }
            mx = fmaxf(mx, __shfl_xor_sync(0xffffffffu, mx, 1));
            mx = fmaxf(mx, __shfl_xor_sync(0xffffffffu, mx, 2));
            if ((l & 3) == 0) s_red[wn][rl] = mx;
        }
    }
    __syncthreads();
    {
        float m = fmaxf(s_red[0][tid], s_red[1][tid]);
        int grow = mtile * 128 + tid;
        if (grow < NN) {
            float neg = sqrtf(fmaxf(2.f - 2.f * m, EPSF));
            atomicMin(&g_negMinI[b * NN + grow], __float_as_int(neg));
        }
    }

    // last block: deterministic final reduction
    __syncthreads();
    if (tid == 0) {
        __threadfence();
        s_last = (atomicAdd(&g_ctr, 1u) == TOTALB - 1) ? 1 : 0;
    }
    __syncthreads();
    if (s_last) {
        __threadfence();
        float aL = 0.f, aM = 0.f;
        for (int i = tid; i < BQ * NN; i += 128) {
            float neg = __int_as_float(g_negMinI[i]);
            float lv = fmaxf(g_posSim[i] - neg + 1.0f, 0.f);
            float mm = g_match[i];
            aL += lv * lv * mm;
            aM += mm;
        }
#pragma unroll
        for (int off = 16; off; off >>= 1) {
            aL += __shfl_xor_sync(0xffffffffu, aL, off);
            aM += __shfl_xor_sync(0xffffffffu, aM, off);
        }
        if (l == 0) { rL[wid] = aL; rM[wid] = aM; }
        __syncthreads();
        if (tid == 0) {
            float sL = 0.f, sM = 0.f;
#pragma unroll
            for (int q = 0; q < 4; ++q) { sL += rL[q]; sM += rM[q]; }
            out[0] = sL / sM;
        }
    }
}

// ---------------- launch ----------------
extern "C" void kernel_launch(void* const* d_in, const int* in_sizes, int n_in,
                              void* d_out, int out_size) {
    // metadata order: score1, score2, desc1, desc2, homo12, homo21
    const float* desc1  = (const float*)d_in[2];
    const float* desc2  = (const float*)d_in[3];
    const float* homo12 = (const float*)d_in[4];
    const float* homo21 = (const float*)d_in[5];

    cudaFuncSetAttribute(mma_kernel, cudaFuncAttributeMaxDynamicSharedMemorySize,
                         SMEM_BYTES);
    prep_kernel<<<(BQ * NN + 255) / 256, 256>>>(desc1, desc2, homo12, homo21);
    split_kernel<<<dim3(MT, BQ), 256>>>(desc1, desc2);
    dim3 g(MT, MT, BQ);
    mma_kernel<<<g, 128, SMEM_BYTES>>>((float*)d_out);
}

// round 10
// speedup vs baseline: 4.4403x; 1.0097x over previous
#include <cuda_runtime.h>
#include <cuda_fp16.h>
#include <math.h>
#include <stdint.h>

// Problem constants (b=2, c=64, H=480, W=640, gs=8 -> hc=60, wc=80, n=4800)
#define BQ 2
#define CC 64
#define HC 60
#define WCC 80
#define NN 4800
#define HH 480
#define WW 640
#define EPSF 1e-8f
#define NEGBIG -1e30f

// GEMM: M=N=4800 (pad 4864), K=128 fp16 (hi|lo split), 128x128 tiles
#define KH 128
#define NPAD 4864
#define MT 38
#define TOTALB (MT * MT * BQ)          // 2888
#define ROWB 272                       // 17 x 16B, odd -> conflict-free
#define CHUNK (128 * ROWB)             // 34816 bytes per matrix tile
#define SMEM_BYTES (2 * CHUNK)         // 69632

// ---------------- scratch (no allocations allowed) ----------------
__device__ float    g_visNeg[BQ * NN];     // 0 if visible else -1e30
__device__ float    g_posSim[BQ * NN];
__device__ float    g_match[BQ * NN];
__device__ int      g_neigh[BQ * NN * 4];
__device__ int      g_negMinI[BQ * NN];
__device__ unsigned g_ctr;
__device__ __align__(16) __half g_Ah[(size_t)BQ * NPAD * KH];
__device__ __align__(16) __half g_Bh[(size_t)BQ * NPAD * KH];

__device__ __forceinline__ uint32_t smem_u32(const void* p) {
    uint32_t a;
    asm("{ .reg .u64 t; cvta.to.shared.u64 t, %1; cvt.u32.u64 %0, t; }"
        : "=r"(a) : "l"(p));
    return a;
}
__device__ __forceinline__ void ldsm4(uint32_t* r, uint32_t addr) {
    asm volatile("ldmatrix.sync.aligned.m8n8.x4.shared.b16 {%0,%1,%2,%3}, [%4];"
                 : "=r"(r[0]), "=r"(r[1]), "=r"(r[2]), "=r"(r[3]) : "r"(addr));
}
__device__ __forceinline__ void mma16816(float* c, const uint32_t* a,
                                         uint32_t b0, uint32_t b1) {
    asm volatile(
        "mma.sync.aligned.m16n8k16.row.col.f32.f16.f16.f32 "
        "{%0,%1,%2,%3}, {%4,%5,%6,%7}, {%8,%9}, {%0,%1,%2,%3};"
        : "+f"(c[0]), "+f"(c[1]), "+f"(c[2]), "+f"(c[3])
        : "r"(a[0]), "r"(a[1]), "r"(a[2]), "r"(a[3]), "r"(b0), "r"(b1));
}
__device__ __forceinline__ void cp16(uint32_t dst, const void* src) {
    asm volatile("cp.async.cg.shared.global [%0], [%1], 16;"
                 :: "r"(dst), "l"(src) : "memory");
}
#define CP_COMMIT() asm volatile("cp.async.commit_group;" ::: "memory")
#define CP_WAIT(n)  asm volatile("cp.async.wait_group %0;" :: "n"(n) : "memory")

__device__ __forceinline__ float inb_grid(float yi, float xi) {
    return (yi >= 0.f && yi <= (float)(HC - 1) && xi >= 0.f && xi <= (float)(WCC - 1)) ? 1.f : 0.f;
}

// ====== Kernel 0: per-row prep, 4 THREADS per row (parallel + coalesced) ====
__global__ void prep_kernel(const float* __restrict__ desc1,
                            const float* __restrict__ desc2,
                            const float* __restrict__ homo12,
                            const float* __restrict__ homo21) {
    int t4 = blockIdx.x * 256 + threadIdx.x;
    if (t4 == 0) g_ctr = 0u;
    int t = t4 >> 2;          // global row id (b*NN + r)
    int p = t4 & 3;           // part 0..3
    if (t >= BQ * NN) return;
    int b = t / NN, r = t % NN;
    int iy = r / WCC, ix = r % WCC;

    // ---- visibility: 16 of 64 cell pixels per part, division-free ----
    unsigned oku;
    {
        const float* h = homo21 + b * 9;
        float h0 = h[0], h1 = h[1], h2 = h[2], h3 = h[3], h4 = h[4],
              h5 = h[5], h6 = h[6], h7 = h[7], h8 = h[8];
        float cx0 = (float)(ix * 8), cy0 = (float)(iy * 8);
        bool ok = true;
#pragma unroll
        for (int dyy = 0; dyy < 2; ++dyy) {
            float y = cy0 + (float)(p * 2 + dyy);
            float qxr = h0 * cx0 + h1 * y + h2;
            float qyr = h3 * cx0 + h4 * y + h5;
            float qzr = h6 * cx0 + h7 * y + h8;
#pragma unroll
            for (int dx = 0; dx < 8; ++dx) {
                float qx = qxr + h0 * (float)dx;
                float qy = qyr + h3 * (float)dx;
                float z  = qzr + h6 * (float)dx + EPSF;
                ok = ok && ((qy + z) * z > 0.f)
                        && (((float)HH * z - qy) * z > 0.f)
                        && ((qx + z) * z > 0.f)
                        && (((float)WW * z - qx) * z > 0.f);
            }
        }
        oku = ok ? 1u : 0u;
        oku &= __shfl_xor_sync(0xffffffffu, oku, 1);
        oku &= __shfl_xor_sync(0xffffffffu, oku, 2);
        if (p == 0) {
            g_visNeg[t] = oku ? 0.f : NEGBIG;
            g_negMinI[t] = 0x7F800000;
        }
    }

    // ---- warp point under homo12 (all parts, cheap) ----
    const float* h = homo12 + b * 9;
    float px = (float)(ix * 8) + 3.5f;
    float py = (float)(iy * 8) + 3.5f;
    float qx = h[0] * px + h[1] * py + h[2];
    float qy = h[3] * px + h[4] * py + h[5];
    float qz = h[6] * px + h[7] * py + h[8];
    float wx = qx / (qz + EPSF);
    float wy = qy / (qz + EPSF);
    float dyc = (wy - 3.5f) * 0.125f;
    float dxc = (wx - 3.5f) * 0.125f;

    // ---- 4-NN in clamped 4x4 window (part 0 only; tie -> lower index) ----
    if (p == 0) {
        float a2 = wy * wy + wx * wx;
        int xlo = (int)fminf(fmaxf(floorf(dxc) - 1.f, 0.f), (float)(WCC - 4));
        int ylo = (int)fminf(fmaxf(floorf(dyc) - 1.f, 0.f), (float)(HC - 4));
        float bd[4] = {1e30f, 1e30f, 1e30f, 1e30f};
        int bi[4] = {-1, -1, -1, -1};
#pragma unroll
        for (int jy = 0; jy < 4; ++jy) {
            int iyc = ylo + jy;
            float cy = (float)(iyc * 8) + 3.5f;
#pragma unroll
            for (int jx = 0; jx < 4; ++jx) {
                int ixc = xlo + jx;
                float cx = (float)(ixc * 8) + 3.5f;
                float d = a2 + cy * cy + cx * cx - 2.f * (wy * cy + wx * cx);
                int m = iyc * WCC + ixc;
                if (d < bd[3]) {
                    int k = 3;
                    while (k > 0 && d < bd[k - 1]) {
                        bd[k] = bd[k - 1]; bi[k] = bi[k - 1]; --k;
                    }
                    bd[k] = d; bi[k] = m;
                }
            }
        }
        int* o = &g_neigh[(size_t)t * 4];
        o[0] = bi[0]; o[1] = bi[1]; o[2] = bi[2]; o[3] = bi[3];
    }

    // ---- bilinear w_desc1 + pos_sim: 16 channels per part ----
    float y0 = floorf(dyc), x0 = floorf(dxc);
    float fy = dyc - y0, fx = dxc - x0;
    float e00 = (1.f - fy) * (1.f - fx) * inb_grid(y0, x0);
    float e01 = (1.f - fy) * fx         * inb_grid(y0, x0 + 1.f);
    float e10 = fy * (1.f - fx)         * inb_grid(y0 + 1.f, x0);
    float e11 = fy * fx                 * inb_grid(y0 + 1.f, x0 + 1.f);
    int yc0 = (int)fminf(fmaxf(y0, 0.f), (float)(HC - 1));
    int yc1 = (int)fminf(fmaxf(y0 + 1.f, 0.f), (float)(HC - 1));
    int xc0 = (int)fminf(fmaxf(x0, 0.f), (float)(WCC - 1));
    int xc1 = (int)fminf(fmaxf(x0 + 1.f, 0.f), (float)(WCC - 1));
    int c00 = yc0 * WCC + xc0, c01 = yc0 * WCC + xc1;
    int c10 = yc1 * WCC + xc0, c11 = yc1 * WCC + xc1;

    const float* d2b = desc2 + ((size_t)b * CC + p * 16) * NN;
    const float* d1b = desc1 + ((size_t)b * CC + p * 16) * NN + r;
    float sq = 0.f, dp = 0.f;
#pragma unroll 4
    for (int i = 0; i < 16; ++i) {
        const float* pp = d2b + (size_t)i * NN;
        float v = e00 * pp[c00] + e01 * pp[c01] + e10 * pp[c10] + e11 * pp[c11];
        sq += v * v;
        dp += d1b[(size_t)i * NN] * v;
    }
    sq += __shfl_xor_sync(0xffffffffu, sq, 1);
    dp += __shfl_xor_sync(0xffffffffu, dp, 1);
    sq += __shfl_xor_sync(0xffffffffu, sq, 2);
    dp += __shfl_xor_sync(0xffffffffu, dp, 2);

    if (p == 0) {
        float posdot = dp / (sqrtf(sq) + EPSF);
        g_posSim[t] = sqrtf(fmaxf(2.f - 2.f * posdot, EPSF));
        g_match[t] =
            (wy >= 0.f && wy <= (float)(HH - 1) && wx >= 0.f && wx <= (float)(WW - 1)) ? 1.f : 0.f;
    }
}

// ====== Kernel 1: f32 -> fp16 hi|lo split scratch (K = 64 hi + 64 lo) ======
__global__ void split_kernel(const float* __restrict__ desc1,
                             const float* __restrict__ desc2) {
    __shared__ float sd[CC][129];
    int b = blockIdx.y;
    int row0 = blockIdx.x * 128;
    int tid = threadIdx.x;   // 256 threads

    for (int i = tid; i < CC * 128; i += 256) {
        int ch = i >> 7, r = i & 127;
        int gr = row0 + r;
        sd[ch][r] = (gr < NN) ? desc1[(size_t)(b * CC + ch) * NN + gr] : 0.f;
    }
    __syncthreads();
    for (int i = tid; i < 128 * KH; i += 256) {
        int r = i >> 7, k = i & 127;
        float v = sd[k & 63][r];
        __half hi = __float2half_rn(v);
        __half o = (k < 64) ? hi : __float2half_rn(v - __half2float(hi));
        g_Ah[((size_t)b * NPAD + row0 + r) * KH + k] = o;
    }
    __syncthreads();

    for (int i = tid; i < CC * 128; i += 256) {
        int ch = i >> 7, r = i & 127;
        int gr = row0 + r;
        sd[ch][r] = (gr < NN) ? desc2[(size_t)(b * CC + ch) * NN + gr] : 0.f;
    }
    __syncthreads();
    for (int i = tid; i < 128 * KH; i += 256) {
        int r = i >> 7, k = i & 127;
        float v = sd[k & 63][r];
        __half hi = __float2half_rn(v);
        __half o = (k < 64) ? hi : __float2half_rn(v - __half2float(hi));
        g_Bh[((size_t)b * NPAD + row0 + r) * KH + k] = o;
    }
}

// ====== Kernel 2: fp16 GEMM, 4-chunk k-pipelined cp.async + epilogue ======
__global__ void __launch_bounds__(128, 2)
mma_kernel(float* __restrict__ out) {
    extern __shared__ char sm[];
    __shared__ int4  s_nb[128];
    __shared__ float s_vs[128];
    __shared__ float s_red[2][128];
    __shared__ int   s_last;
    __shared__ float rL[4], rM[4];

    int tid = threadIdx.x;
    int wid = tid >> 5, l = tid & 31;
    int wm = wid & 1, wn = wid >> 1;        // 2 x 2 warp grid
    int ntile = blockIdx.x, mtile = blockIdx.y, b = blockIdx.z;

    uint32_t au = smem_u32(sm);
    const __half* Asrc = g_Ah + ((size_t)b * NPAD + mtile * 128) * KH;
    const __half* Bsrc = g_Bh + ((size_t)b * NPAD + ntile * 128) * KH;

    // issue K in 4 chunks of 32 halves (4 x 16B per row), one group per chunk
#pragma unroll
    for (int c = 0; c < 4; ++c) {
#pragma unroll
        for (int q = 0; q < 4; ++q) {
            int i = q * 128 + tid;              // 0..511
            int rr = i >> 2, g = (i & 3) + c * 4;
            cp16(au + rr * ROWB + g * 16, Asrc + (size_t)rr * KH + g * 8);
        }
#pragma unroll
        for (int q = 0; q < 4; ++q) {
            int i = q * 128 + tid;
            int rr = i >> 2, g = (i & 3) + c * 4;
            cp16(au + CHUNK + rr * ROWB + g * 16, Bsrc + (size_t)rr * KH + g * 8);
        }
        CP_COMMIT();
    }

    // stage neighbor indices + vis while loads fly
    {
        int grow = mtile * 128 + tid;
        int gr = grow < NN ? grow : NN - 1;
        int4 nb = *reinterpret_cast<const int4*>(&g_neigh[((size_t)b * NN + gr) * 4]);
        int cb = ntile * 128;
        nb.x -= cb; nb.y -= cb; nb.z -= cb; nb.w -= cb;
        s_nb[tid] = nb;
        int gcol = ntile * 128 + tid;
        s_vs[tid] = (gcol < NN) ? g_visNeg[b * NN + gcol] : NEGBIG;
    }

    // ldmatrix per-lane row offsets (warp tile 64x64)
    int lane7 = l & 7, mat = l >> 3, kh = mat >> 1;
    uint32_t arow[4], brow[4];
#pragma unroll
    for (int mf = 0; mf < 4; ++mf)
        arow[mf] = (uint32_t)(wm * 64 + mf * 16 + (mat & 1) * 8 + lane7) * ROWB;
#pragma unroll
    for (int bf = 0; bf < 4; ++bf)
        brow[bf] = (uint32_t)(wn * 64 + bf * 16 + (mat & 1) * 8 + lane7) * ROWB + CHUNK;

    float cfr[4][8][4];
#pragma unroll
    for (int mf = 0; mf < 4; ++mf)
#pragma unroll
        for (int nf = 0; nf < 8; ++nf)
#pragma unroll
            for (int q = 0; q < 4; ++q) cfr[mf][nf][q] = 0.f;

    // compute chunk-by-chunk as data lands
#pragma unroll
    for (int c = 0; c < 4; ++c) {
        if (c == 0)      CP_WAIT(3);
        else if (c == 1) CP_WAIT(2);
        else if (c == 2) CP_WAIT(1);
        else             CP_WAIT(0);
        __syncthreads();
#pragma unroll
        for (int k2 = 0; k2 < 2; ++k2) {
            uint32_t g16 = (uint32_t)(((c * 2 + k2) * 2 + kh) << 4);
            uint32_t af[4][4], bq[4][4];
#pragma unroll
            for (int mf = 0; mf < 4; ++mf) ldsm4(af[mf], au + arow[mf] + g16);
#pragma unroll
            for (int bf = 0; bf < 4; ++bf) ldsm4(bq[bf], au + brow[bf] + g16);
#pragma unroll
            for (int mf = 0; mf < 4; ++mf)
#pragma unroll
                for (int nf = 0; nf < 8; ++nf)
                    mma16816(cfr[mf][nf], af[mf],
                             bq[nf >> 1][nf & 1], bq[nf >> 1][2 + (nf & 1)]);
        }
    }

    // epilogue: vis add + neighbor-masked max per row
#pragma unroll
    for (int mf = 0; mf < 4; ++mf) {
#pragma unroll
        for (int half = 0; half < 2; ++half) {
            int rl = wm * 64 + mf * 16 + (l >> 2) + half * 8;
            int4 nb = s_nb[rl];
            float mx = NEGBIG;
#pragma unroll
            for (int nf = 0; nf < 8; ++nf) {
                int c0 = wn * 64 + nf * 8 + (l & 3) * 2;
                int c1 = c0 + 1;
                float v0 = cfr[mf][nf][half * 2 + 0] + s_vs[c0];
                float v1 = cfr[mf][nf][half * 2 + 1] + s_vs[c1];
                bool m0 = (nb.x == c0) | (nb.y == c0) | (nb.z == c0) | (nb.w == c0);
                bool m1 = (nb.x == c1) | (nb.y == c1) | (nb.z == c1) | (nb.w == c1);
                mx = fmaxf(mx, m0 ? NEGBIG : v0);
                mx = fmaxf(mx, m1 ? NEGBIG : v1);
            }
            mx = fmaxf(mx, __shfl_xor_sync(0xffffffffu, mx, 1));
            mx = fmaxf(mx, __shfl_xor_sync(0xffffffffu, mx, 2));
            if ((l & 3) == 0) s_red[wn][rl] = mx;
        }
    }
    __syncthreads();
    {
        float m = fmaxf(s_red[0][tid], s_red[1][tid]);
        int grow = mtile * 128 + tid;
        if (grow < NN) {
            float neg = sqrtf(fmaxf(2.f - 2.f * m, EPSF));
            atomicMin(&g_negMinI[b * NN + grow], __float_as_int(neg));
        }
    }

    // last block: deterministic final reduction
    __syncthreads();
    if (tid == 0) {
        __threadfence();
        s_last = (atomicAdd(&g_ctr, 1u) == TOTALB - 1) ? 1 : 0;
    }
    __syncthreads();
    if (s_last) {
        __threadfence();
        float aL = 0.f, aM = 0.f;
        for (int i = tid; i < BQ * NN; i += 128) {
            float neg = __int_as_float(g_negMinI[i]);
            float lv = fmaxf(g_posSim[i] - neg + 1.0f, 0.f);
            float mm = g_match[i];
            aL += lv * lv * mm;
            aM += mm;
        }
#pragma unroll
        for (int off = 16; off; off >>= 1) {
            aL += __shfl_xor_sync(0xffffffffu, aL, off);
            aM += __shfl_xor_sync(0xffffffffu, aM, off);
        }
        if (l == 0) { rL[wid] = aL; rM[wid] = aM; }
        __syncthreads();
        if (tid == 0) {
            float sL = 0.f, sM = 0.f;
#pragma unroll
            for (int q = 0; q < 4; ++q) { sL += rL[q]; sM += rM[q]; }
            out[0] = sL / sM;
        }
    }
}

// ---------------- launch ----------------
extern "C" void kernel_launch(void* const* d_in, const int* in_sizes, int n_in,
                              void* d_out, int out_size) {
    // metadata order: score1, score2, desc1, desc2, homo12, homo21
    const float* desc1  = (const float*)d_in[2];
    const float* desc2  = (const float*)d_in[3];
    const float* homo12 = (const float*)d_in[4];
    const float* homo21 = (const float*)d_in[5];

    cudaFuncSetAttribute(mma_kernel, cudaFuncAttributeMaxDynamicSharedMemorySize,
                         SMEM_BYTES);
    prep_kernel<<<(BQ * NN * 4 + 255) / 256, 256>>>(desc1, desc2, homo12, homo21);
    split_kernel<<<dim3(MT, BQ), 256>>>(desc1, desc2);
    dim3 g(MT, MT, BQ);
    mma_kernel<<<g, 128, SMEM_BYTES>>>((float*)d_out);
}

// round 11
// speedup vs baseline: 4.5804x; 1.0316x over previous
#include <cuda_runtime.h>
#include <cuda_fp16.h>
#include <math.h>
#include <stdint.h>

// Problem constants (b=2, c=64, H=480, W=640, gs=8 -> hc=60, wc=80, n=4800)
#define BQ 2
#define CC 64
#define HC 60
#define WCC 80
#define NN 4800
#define HH 480
#define WW 640
#define EPSF 1e-8f
#define NEGBIG -1e30f

// GEMM: M=N=4800 (pad 4864), K=128 fp16 (hi|lo split), 128x128 tiles
#define KH 128
#define NPAD 4864
#define MT 38
#define TOTALB (MT * MT * BQ)          // 2888
#define ROWB 272                       // 17 x 16B, odd -> conflict-free
#define CHUNK (128 * ROWB)             // 34816 bytes per matrix tile
#define SMEM_BYTES (2 * CHUNK)         // 69632

// ---------------- scratch (no allocations allowed) ----------------
__device__ float    g_visNeg[BQ * NN];     // 0 if visible else -1e30
__device__ float    g_posSim[BQ * NN];
__device__ float    g_match[BQ * NN];
__device__ int      g_neigh[BQ * NN * 4];
__device__ int      g_negMinI[BQ * NN];
__device__ unsigned g_ctr;
__device__ __align__(16) __half g_Ah[(size_t)BQ * NPAD * KH];
__device__ __align__(16) __half g_Bh[(size_t)BQ * NPAD * KH];

__device__ __forceinline__ uint32_t smem_u32(const void* p) {
    uint32_t a;
    asm("{ .reg .u64 t; cvta.to.shared.u64 t, %1; cvt.u32.u64 %0, t; }"
        : "=r"(a) : "l"(p));
    return a;
}
__device__ __forceinline__ void ldsm4(uint32_t* r, uint32_t addr) {
    asm volatile("ldmatrix.sync.aligned.m8n8.x4.shared.b16 {%0,%1,%2,%3}, [%4];"
                 : "=r"(r[0]), "=r"(r[1]), "=r"(r[2]), "=r"(r[3]) : "r"(addr));
}
__device__ __forceinline__ void mma16816(float* c, const uint32_t* a,
                                         uint32_t b0, uint32_t b1) {
    asm volatile(
        "mma.sync.aligned.m16n8k16.row.col.f32.f16.f16.f32 "
        "{%0,%1,%2,%3}, {%4,%5,%6,%7}, {%8,%9}, {%0,%1,%2,%3};"
        : "+f"(c[0]), "+f"(c[1]), "+f"(c[2]), "+f"(c[3])
        : "r"(a[0]), "r"(a[1]), "r"(a[2]), "r"(a[3]), "r"(b0), "r"(b1));
}
__device__ __forceinline__ void cp16(uint32_t dst, const void* src) {
    asm volatile("cp.async.cg.shared.global [%0], [%1], 16;"
                 :: "r"(dst), "l"(src) : "memory");
}
#define CP_COMMIT() asm volatile("cp.async.commit_group;" ::: "memory")
#define CP_WAIT(n)  asm volatile("cp.async.wait_group %0;" :: "n"(n) : "memory")

__device__ __forceinline__ float inb_grid(float yi, float xi) {
    return (yi >= 0.f && yi <= (float)(HC - 1) && xi >= 0.f && xi <= (float)(WCC - 1)) ? 1.f : 0.f;
}

// ====== Kernel 0: per-row prep, 8 THREADS per row (parallel + coalesced) ====
__global__ void prep_kernel(const float* __restrict__ desc1,
                            const float* __restrict__ desc2,
                            const float* __restrict__ homo12,
                            const float* __restrict__ homo21) {
    int t8 = blockIdx.x * 256 + threadIdx.x;
    if (t8 == 0) g_ctr = 0u;
    int t = t8 >> 3;          // global row id (b*NN + r)
    int p = t8 & 7;           // part 0..7
    if (t >= BQ * NN) return;
    int b = t / NN, r = t % NN;
    int iy = r / WCC, ix = r % WCC;

    // ---- visibility: one dy-row of 8 pixels per part, division-free ----
    {
        const float* h = homo21 + b * 9;
        float h0 = h[0], h1 = h[1], h2 = h[2], h3 = h[3], h4 = h[4],
              h5 = h[5], h6 = h[6], h7 = h[7], h8 = h[8];
        float cx0 = (float)(ix * 8);
        float y = (float)(iy * 8 + p);
        float qxr = h0 * cx0 + h1 * y + h2;
        float qyr = h3 * cx0 + h4 * y + h5;
        float qzr = h6 * cx0 + h7 * y + h8;
        bool ok = true;
#pragma unroll
        for (int dx = 0; dx < 8; ++dx) {
            float qx = qxr + h0 * (float)dx;
            float qy = qyr + h3 * (float)dx;
            float z  = qzr + h6 * (float)dx + EPSF;
            ok = ok && ((qy + z) * z > 0.f)
                    && (((float)HH * z - qy) * z > 0.f)
                    && ((qx + z) * z > 0.f)
                    && (((float)WW * z - qx) * z > 0.f);
        }
        unsigned oku = ok ? 1u : 0u;
        oku &= __shfl_xor_sync(0xffffffffu, oku, 1);
        oku &= __shfl_xor_sync(0xffffffffu, oku, 2);
        oku &= __shfl_xor_sync(0xffffffffu, oku, 4);
        if (p == 0) {
            g_visNeg[t] = oku ? 0.f : NEGBIG;
            g_negMinI[t] = 0x7F800000;
        }
    }

    // ---- warp point under homo12 (all parts, cheap) ----
    const float* h = homo12 + b * 9;
    float px = (float)(ix * 8) + 3.5f;
    float py = (float)(iy * 8) + 3.5f;
    float qx = h[0] * px + h[1] * py + h[2];
    float qy = h[3] * px + h[4] * py + h[5];
    float qz = h[6] * px + h[7] * py + h[8];
    float wx = qx / (qz + EPSF);
    float wy = qy / (qz + EPSF);
    float dyc = (wy - 3.5f) * 0.125f;
    float dxc = (wx - 3.5f) * 0.125f;

    // ---- 4-NN in clamped 4x4 window (part 0 only; tie -> lower index) ----
    if (p == 0) {
        float a2 = wy * wy + wx * wx;
        int xlo = (int)fminf(fmaxf(floorf(dxc) - 1.f, 0.f), (float)(WCC - 4));
        int ylo = (int)fminf(fmaxf(floorf(dyc) - 1.f, 0.f), (float)(HC - 4));
        float bd[4] = {1e30f, 1e30f, 1e30f, 1e30f};
        int bi[4] = {-1, -1, -1, -1};
#pragma unroll
        for (int jy = 0; jy < 4; ++jy) {
            int iyc = ylo + jy;
            float cy = (float)(iyc * 8) + 3.5f;
#pragma unroll
            for (int jx = 0; jx < 4; ++jx) {
                int ixc = xlo + jx;
                float cx = (float)(ixc * 8) + 3.5f;
                float d = a2 + cy * cy + cx * cx - 2.f * (wy * cy + wx * cx);
                int m = iyc * WCC + ixc;
                if (d < bd[3]) {
                    int k = 3;
                    while (k > 0 && d < bd[k - 1]) {
                        bd[k] = bd[k - 1]; bi[k] = bi[k - 1]; --k;
                    }
                    bd[k] = d; bi[k] = m;
                }
            }
        }
        int* o = &g_neigh[(size_t)t * 4];
        o[0] = bi[0]; o[1] = bi[1]; o[2] = bi[2]; o[3] = bi[3];
    }

    // ---- bilinear w_desc1 + pos_sim: 8 channels per part ----
    float y0 = floorf(dyc), x0 = floorf(dxc);
    float fy = dyc - y0, fx = dxc - x0;
    float e00 = (1.f - fy) * (1.f - fx) * inb_grid(y0, x0);
    float e01 = (1.f - fy) * fx         * inb_grid(y0, x0 + 1.f);
    float e10 = fy * (1.f - fx)         * inb_grid(y0 + 1.f, x0);
    float e11 = fy * fx                 * inb_grid(y0 + 1.f, x0 + 1.f);
    int yc0 = (int)fminf(fmaxf(y0, 0.f), (float)(HC - 1));
    int yc1 = (int)fminf(fmaxf(y0 + 1.f, 0.f), (float)(HC - 1));
    int xc0 = (int)fminf(fmaxf(x0, 0.f), (float)(WCC - 1));
    int xc1 = (int)fminf(fmaxf(x0 + 1.f, 0.f), (float)(WCC - 1));
    int c00 = yc0 * WCC + xc0, c01 = yc0 * WCC + xc1;
    int c10 = yc1 * WCC + xc0, c11 = yc1 * WCC + xc1;

    const float* d2b = desc2 + ((size_t)b * CC + p * 8) * NN;
    const float* d1b = desc1 + ((size_t)b * CC + p * 8) * NN + r;
    float sq = 0.f, dp = 0.f;
#pragma unroll
    for (int i = 0; i < 8; ++i) {
        const float* pp = d2b + (size_t)i * NN;
        float v = e00 * pp[c00] + e01 * pp[c01] + e10 * pp[c10] + e11 * pp[c11];
        sq += v * v;
        dp += d1b[(size_t)i * NN] * v;
    }
    sq += __shfl_xor_sync(0xffffffffu, sq, 1);
    dp += __shfl_xor_sync(0xffffffffu, dp, 1);
    sq += __shfl_xor_sync(0xffffffffu, sq, 2);
    dp += __shfl_xor_sync(0xffffffffu, dp, 2);
    sq += __shfl_xor_sync(0xffffffffu, sq, 4);
    dp += __shfl_xor_sync(0xffffffffu, dp, 4);

    if (p == 0) {
        float posdot = dp / (sqrtf(sq) + EPSF);
        g_posSim[t] = sqrtf(fmaxf(2.f - 2.f * posdot, EPSF));
        g_match[t] =
            (wy >= 0.f && wy <= (float)(HH - 1) && wx >= 0.f && wx <= (float)(WW - 1)) ? 1.f : 0.f;
    }
}

// ====== Kernel 1: f32 -> fp16 hi|lo split scratch (K = 64 hi + 64 lo) ======
__global__ void split_kernel(const float* __restrict__ desc1,
                             const float* __restrict__ desc2) {
    __shared__ float sd[CC][129];
    int b = blockIdx.y;
    int row0 = blockIdx.x * 128;
    int tid = threadIdx.x;   // 256 threads

    for (int i = tid; i < CC * 128; i += 256) {
        int ch = i >> 7, r = i & 127;
        int gr = row0 + r;
        sd[ch][r] = (gr < NN) ? desc1[(size_t)(b * CC + ch) * NN + gr] : 0.f;
    }
    __syncthreads();
    for (int i = tid; i < 128 * KH; i += 256) {
        int r = i >> 7, k = i & 127;
        float v = sd[k & 63][r];
        __half hi = __float2half_rn(v);
        __half o = (k < 64) ? hi : __float2half_rn(v - __half2float(hi));
        g_Ah[((size_t)b * NPAD + row0 + r) * KH + k] = o;
    }
    __syncthreads();

    for (int i = tid; i < CC * 128; i += 256) {
        int ch = i >> 7, r = i & 127;
        int gr = row0 + r;
        sd[ch][r] = (gr < NN) ? desc2[(size_t)(b * CC + ch) * NN + gr] : 0.f;
    }
    __syncthreads();
    for (int i = tid; i < 128 * KH; i += 256) {
        int r = i >> 7, k = i & 127;
        float v = sd[k & 63][r];
        __half hi = __float2half_rn(v);
        __half o = (k < 64) ? hi : __float2half_rn(v - __half2float(hi));
        g_Bh[((size_t)b * NPAD + row0 + r) * KH + k] = o;
    }
}

// ====== Kernel 2: fp16 GEMM, 4 warps, 64x64 warp tiles + epilogue ======
__global__ void __launch_bounds__(128, 2)
mma_kernel(float* __restrict__ out) {
    extern __shared__ char sm[];
    __shared__ int4  s_nb[128];
    __shared__ float s_vs[128];
    __shared__ float s_red[2][128];
    __shared__ int   s_last;
    __shared__ float rL[4], rM[4];

    int tid = threadIdx.x;
    int wid = tid >> 5, l = tid & 31;
    int wm = wid & 1, wn = wid >> 1;        // 2 x 2 warp grid
    int ntile = blockIdx.x, mtile = blockIdx.y, b = blockIdx.z;

    uint32_t au = smem_u32(sm);
    const __half* Asrc = g_Ah + ((size_t)b * NPAD + mtile * 128) * KH;
    const __half* Bsrc = g_Bh + ((size_t)b * NPAD + ntile * 128) * KH;

    // full-K tiles via cp.async: 16 x 16B contiguous chunks per row
#pragma unroll
    for (int tq = 0; tq < 16; ++tq) {
        int i = tq * 128 + tid, rr = i >> 4, g = i & 15;
        cp16(au + rr * ROWB + g * 16, Asrc + (size_t)rr * KH + g * 8);
    }
#pragma unroll
    for (int tq = 0; tq < 16; ++tq) {
        int i = tq * 128 + tid, rr = i >> 4, g = i & 15;
        cp16(au + CHUNK + rr * ROWB + g * 16, Bsrc + (size_t)rr * KH + g * 8);
    }
    CP_COMMIT();

    // stage neighbor indices + vis while loads fly
    {
        int grow = mtile * 128 + tid;
        int gr = grow < NN ? grow : NN - 1;
        int4 nb = *reinterpret_cast<const int4*>(&g_neigh[((size_t)b * NN + gr) * 4]);
        int cb = ntile * 128;
        nb.x -= cb; nb.y -= cb; nb.z -= cb; nb.w -= cb;
        s_nb[tid] = nb;
        int gcol = ntile * 128 + tid;
        s_vs[tid] = (gcol < NN) ? g_visNeg[b * NN + gcol] : NEGBIG;
    }

    // ldmatrix per-lane row offsets (warp tile 64x64)
    int lane7 = l & 7, mat = l >> 3, kh = mat >> 1;
    uint32_t arow[4], brow[4];
#pragma unroll
    for (int mf = 0; mf < 4; ++mf)
        arow[mf] = (uint32_t)(wm * 64 + mf * 16 + (mat & 1) * 8 + lane7) * ROWB;
#pragma unroll
    for (int bf = 0; bf < 4; ++bf)
        brow[bf] = (uint32_t)(wn * 64 + bf * 16 + (mat & 1) * 8 + lane7) * ROWB + CHUNK;

    float cfr[4][8][4];
#pragma unroll
    for (int mf = 0; mf < 4; ++mf)
#pragma unroll
        for (int nf = 0; nf < 8; ++nf)
#pragma unroll
            for (int q = 0; q < 4; ++q) cfr[mf][nf][q] = 0.f;

    CP_WAIT(0);
    __syncthreads();

#pragma unroll
    for (int ks = 0; ks < 8; ++ks) {
        uint32_t g16 = (uint32_t)((ks * 2 + kh) << 4);
        uint32_t af[4][4], bq[4][4];
#pragma unroll
        for (int mf = 0; mf < 4; ++mf) ldsm4(af[mf], au + arow[mf] + g16);
#pragma unroll
        for (int bf = 0; bf < 4; ++bf) ldsm4(bq[bf], au + brow[bf] + g16);
#pragma unroll
        for (int mf = 0; mf < 4; ++mf)
#pragma unroll
            for (int nf = 0; nf < 8; ++nf)
                mma16816(cfr[mf][nf], af[mf],
                         bq[nf >> 1][nf & 1], bq[nf >> 1][2 + (nf & 1)]);
    }

    // epilogue: vis add + neighbor-masked max per row
#pragma unroll
    for (int mf = 0; mf < 4; ++mf) {
#pragma unroll
        for (int half = 0; half < 2; ++half) {
            int rl = wm * 64 + mf * 16 + (l >> 2) + half * 8;
            int4 nb = s_nb[rl];
            float mx = NEGBIG;
#pragma unroll
            for (int nf = 0; nf < 8; ++nf) {
                int c0 = wn * 64 + nf * 8 + (l & 3) * 2;
                int c1 = c0 + 1;
                float v0 = cfr[mf][nf][half * 2 + 0] + s_vs[c0];
                float v1 = cfr[mf][nf][half * 2 + 1] + s_vs[c1];
                bool m0 = (nb.x == c0) | (nb.y == c0) | (nb.z == c0) | (nb.w == c0);
                bool m1 = (nb.x == c1) | (nb.y == c1) | (nb.z == c1) | (nb.w == c1);
                mx = fmaxf(mx, m0 ? NEGBIG : v0);
                mx = fmaxf(mx, m1 ? NEGBIG : v1);
            }
            mx = fmaxf(mx, __shfl_xor_sync(0xffffffffu, mx, 1));
            mx = fmaxf(mx, __shfl_xor_sync(0xffffffffu, mx, 2));
            if ((l & 3) == 0) s_red[wn][rl] = mx;
        }
    }
    __syncthreads();
    {
        float m = fmaxf(s_red[0][tid], s_red[1][tid]);
        int grow = mtile * 128 + tid;
        if (grow < NN) {
            float neg = sqrtf(fmaxf(2.f - 2.f * m, EPSF));
            atomicMin(&g_negMinI[b * NN + grow], __float_as_int(neg));
        }
    }

    // last block: deterministic final reduction
    __syncthreads();
    if (tid == 0) {
        __threadfence();
        s_last = (atomicAdd(&g_ctr, 1u) == TOTALB - 1) ? 1 : 0;
    }
    __syncthreads();
    if (s_last) {
        __threadfence();
        float aL = 0.f, aM = 0.f;
        for (int i = tid; i < BQ * NN; i += 128) {
            float neg = __int_as_float(g_negMinI[i]);
            float lv = fmaxf(g_posSim[i] - neg + 1.0f, 0.f);
            float mm = g_match[i];
            aL += lv * lv * mm;
            aM += mm;
        }
#pragma unroll
        for (int off = 16; off; off >>= 1) {
            aL += __shfl_xor_sync(0xffffffffu, aL, off);
            aM += __shfl_xor_sync(0xffffffffu, aM, off);
        }
        if (l == 0) { rL[wid] = aL; rM[wid] = aM; }
        __syncthreads();
        if (tid == 0) {
            float sL = 0.f, sM = 0.f;
#pragma unroll
            for (int q = 0; q < 4; ++q) { sL += rL[q]; sM += rM[q]; }
            out[0] = sL / sM;
        }
    }
}

// ---------------- launch ----------------
extern "C" void kernel_launch(void* const* d_in, const int* in_sizes, int n_in,
                              void* d_out, int out_size) {
    // metadata order: score1, score2, desc1, desc2, homo12, homo21
    const float* desc1  = (const float*)d_in[2];
    const float* desc2  = (const float*)d_in[3];
    const float* homo12 = (const float*)d_in[4];
    const float* homo21 = (const float*)d_in[5];

    cudaFuncSetAttribute(mma_kernel, cudaFuncAttributeMaxDynamicSharedMemorySize,
                         SMEM_BYTES);
    prep_kernel<<<(BQ * NN * 8 + 255) / 256, 256>>>(desc1, desc2, homo12, homo21);
    split_kernel<<<dim3(MT, BQ), 256>>>(desc1, desc2);
    dim3 g(MT, MT, BQ);
    mma_kernel<<<g, 128, SMEM_BYTES>>>((float*)d_out);
}

// round 12
// speedup vs baseline: 4.7789x; 1.0433x over previous
#include <cuda_runtime.h>
#include <cuda_fp16.h>
#include <math.h>
#include <stdint.h>

// Problem constants (b=2, c=64, H=480, W=640, gs=8 -> hc=60, wc=80, n=4800)
#define BQ 2
#define CC 64
#define HC 60
#define WCC 80
#define NN 4800
#define HH 480
#define WW 640
#define EPSF 1e-8f
#define NEGBIG -1e30f

// GEMM: M=N=4800 (pad 4864), K=128 fp16 (hi|lo split), 128x128 tiles
// Each block: 1 mtile x 2 ntiles (A reused, B double-streamed)
#define KH 128
#define NPAD 4864
#define MT 38
#define NTG 19                         // ntile pairs
#define TOTALB (NTG * MT * BQ)         // 1444
#define ROWB 272                       // 17 x 16B, odd -> conflict-free
#define CHUNK (128 * ROWB)             // 34816 bytes per matrix tile
#define SMEM_BYTES (3 * CHUNK)         // A + B0 + B1 = 104448

// ---------------- scratch (no allocations allowed) ----------------
__device__ float    g_visNeg[BQ * NN];     // 0 if visible else -1e30
__device__ float    g_posSim[BQ * NN];
__device__ float    g_match[BQ * NN];
__device__ int      g_neigh[BQ * NN * 4];
__device__ int      g_negMinI[BQ * NN];
__device__ unsigned g_ctr;
__device__ __align__(16) __half g_Ah[(size_t)BQ * NPAD * KH];
__device__ __align__(16) __half g_Bh[(size_t)BQ * NPAD * KH];

__device__ __forceinline__ uint32_t smem_u32(const void* p) {
    uint32_t a;
    asm("{ .reg .u64 t; cvta.to.shared.u64 t, %1; cvt.u32.u64 %0, t; }"
        : "=r"(a) : "l"(p));
    return a;
}
__device__ __forceinline__ void ldsm4(uint32_t* r, uint32_t addr) {
    asm volatile("ldmatrix.sync.aligned.m8n8.x4.shared.b16 {%0,%1,%2,%3}, [%4];"
                 : "=r"(r[0]), "=r"(r[1]), "=r"(r[2]), "=r"(r[3]) : "r"(addr));
}
__device__ __forceinline__ void mma16816(float* c, const uint32_t* a,
                                         uint32_t b0, uint32_t b1) {
    asm volatile(
        "mma.sync.aligned.m16n8k16.row.col.f32.f16.f16.f32 "
        "{%0,%1,%2,%3}, {%4,%5,%6,%7}, {%8,%9}, {%0,%1,%2,%3};"
        : "+f"(c[0]), "+f"(c[1]), "+f"(c[2]), "+f"(c[3])
        : "r"(a[0]), "r"(a[1]), "r"(a[2]), "r"(a[3]), "r"(b0), "r"(b1));
}
__device__ __forceinline__ void cp16(uint32_t dst, const void* src) {
    asm volatile("cp.async.cg.shared.global [%0], [%1], 16;"
                 :: "r"(dst), "l"(src) : "memory");
}
#define CP_COMMIT() asm volatile("cp.async.commit_group;" ::: "memory")
#define CP_WAIT(n)  asm volatile("cp.async.wait_group %0;" :: "n"(n) : "memory")

__device__ __forceinline__ float inb_grid(float yi, float xi) {
    return (yi >= 0.f && yi <= (float)(HC - 1) && xi >= 0.f && xi <= (float)(WCC - 1)) ? 1.f : 0.f;
}

// ====== Kernel 0: per-row prep, 8 THREADS per row (parallel + coalesced) ====
__global__ void prep_kernel(const float* __restrict__ desc1,
                            const float* __restrict__ desc2,
                            const float* __restrict__ homo12,
                            const float* __restrict__ homo21) {
    int t8 = blockIdx.x * 256 + threadIdx.x;
    if (t8 == 0) g_ctr = 0u;
    int t = t8 >> 3;          // global row id (b*NN + r)
    int p = t8 & 7;           // part 0..7
    if (t >= BQ * NN) return;
    int b = t / NN, r = t % NN;
    int iy = r / WCC, ix = r % WCC;

    // ---- visibility: one dy-row of 8 pixels per part, division-free ----
    {
        const float* h = homo21 + b * 9;
        float h0 = h[0], h1 = h[1], h2 = h[2], h3 = h[3], h4 = h[4],
              h5 = h[5], h6 = h[6], h7 = h[7], h8 = h[8];
        float cx0 = (float)(ix * 8);
        float y = (float)(iy * 8 + p);
        float qxr = h0 * cx0 + h1 * y + h2;
        float qyr = h3 * cx0 + h4 * y + h5;
        float qzr = h6 * cx0 + h7 * y + h8;
        bool ok = true;
#pragma unroll
        for (int dx = 0; dx < 8; ++dx) {
            float qx = qxr + h0 * (float)dx;
            float qy = qyr + h3 * (float)dx;
            float z  = qzr + h6 * (float)dx + EPSF;
            ok = ok && ((qy + z) * z > 0.f)
                    && (((float)HH * z - qy) * z > 0.f)
                    && ((qx + z) * z > 0.f)
                    && (((float)WW * z - qx) * z > 0.f);
        }
        unsigned oku = ok ? 1u : 0u;
        oku &= __shfl_xor_sync(0xffffffffu, oku, 1);
        oku &= __shfl_xor_sync(0xffffffffu, oku, 2);
        oku &= __shfl_xor_sync(0xffffffffu, oku, 4);
        if (p == 0) {
            g_visNeg[t] = oku ? 0.f : NEGBIG;
            g_negMinI[t] = 0x7F800000;
        }
    }

    // ---- warp point under homo12 (all parts, cheap) ----
    const float* h = homo12 + b * 9;
    float px = (float)(ix * 8) + 3.5f;
    float py = (float)(iy * 8) + 3.5f;
    float qx = h[0] * px + h[1] * py + h[2];
    float qy = h[3] * px + h[4] * py + h[5];
    float qz = h[6] * px + h[7] * py + h[8];
    float wx = qx / (qz + EPSF);
    float wy = qy / (qz + EPSF);
    float dyc = (wy - 3.5f) * 0.125f;
    float dxc = (wx - 3.5f) * 0.125f;

    // ---- 4-NN in clamped 4x4 window (part 0 only; tie -> lower index) ----
    if (p == 0) {
        float a2 = wy * wy + wx * wx;
        int xlo = (int)fminf(fmaxf(floorf(dxc) - 1.f, 0.f), (float)(WCC - 4));
        int ylo = (int)fminf(fmaxf(floorf(dyc) - 1.f, 0.f), (float)(HC - 4));
        float bd[4] = {1e30f, 1e30f, 1e30f, 1e30f};
        int bi[4] = {-1, -1, -1, -1};
#pragma unroll
        for (int jy = 0; jy < 4; ++jy) {
            int iyc = ylo + jy;
            float cy = (float)(iyc * 8) + 3.5f;
#pragma unroll
            for (int jx = 0; jx < 4; ++jx) {
                int ixc = xlo + jx;
                float cx = (float)(ixc * 8) + 3.5f;
                float d = a2 + cy * cy + cx * cx - 2.f * (wy * cy + wx * cx);
                int m = iyc * WCC + ixc;
                if (d < bd[3]) {
                    int k = 3;
                    while (k > 0 && d < bd[k - 1]) {
                        bd[k] = bd[k - 1]; bi[k] = bi[k - 1]; --k;
                    }
                    bd[k] = d; bi[k] = m;
                }
            }
        }
        int* o = &g_neigh[(size_t)t * 4];
        o[0] = bi[0]; o[1] = bi[1]; o[2] = bi[2]; o[3] = bi[3];
    }

    // ---- bilinear w_desc1 + pos_sim: 8 channels per part ----
    float y0 = floorf(dyc), x0 = floorf(dxc);
    float fy = dyc - y0, fx = dxc - x0;
    float e00 = (1.f - fy) * (1.f - fx) * inb_grid(y0, x0);
    float e01 = (1.f - fy) * fx         * inb_grid(y0, x0 + 1.f);
    float e10 = fy * (1.f - fx)         * inb_grid(y0 + 1.f, x0);
    float e11 = fy * fx                 * inb_grid(y0 + 1.f, x0 + 1.f);
    int yc0 = (int)fminf(fmaxf(y0, 0.f), (float)(HC - 1));
    int yc1 = (int)fminf(fmaxf(y0 + 1.f, 0.f), (float)(HC - 1));
    int xc0 = (int)fminf(fmaxf(x0, 0.f), (float)(WCC - 1));
    int xc1 = (int)fminf(fmaxf(x0 + 1.f, 0.f), (float)(WCC - 1));
    int c00 = yc0 * WCC + xc0, c01 = yc0 * WCC + xc1;
    int c10 = yc1 * WCC + xc0, c11 = yc1 * WCC + xc1;

    const float* d2b = desc2 + ((size_t)b * CC + p * 8) * NN;
    const float* d1b = desc1 + ((size_t)b * CC + p * 8) * NN + r;
    float sq = 0.f, dp = 0.f;
#pragma unroll
    for (int i = 0; i < 8; ++i) {
        const float* pp = d2b + (size_t)i * NN;
        float v = e00 * pp[c00] + e01 * pp[c01] + e10 * pp[c10] + e11 * pp[c11];
        sq += v * v;
        dp += d1b[(size_t)i * NN] * v;
    }
    sq += __shfl_xor_sync(0xffffffffu, sq, 1);
    dp += __shfl_xor_sync(0xffffffffu, dp, 1);
    sq += __shfl_xor_sync(0xffffffffu, sq, 2);
    dp += __shfl_xor_sync(0xffffffffu, dp, 2);
    sq += __shfl_xor_sync(0xffffffffu, sq, 4);
    dp += __shfl_xor_sync(0xffffffffu, dp, 4);

    if (p == 0) {
        float posdot = dp / (sqrtf(sq) + EPSF);
        g_posSim[t] = sqrtf(fmaxf(2.f - 2.f * posdot, EPSF));
        g_match[t] =
            (wy >= 0.f && wy <= (float)(HH - 1) && wx >= 0.f && wx <= (float)(WW - 1)) ? 1.f : 0.f;
    }
}

// ====== Kernel 1: f32 -> fp16 hi|lo split scratch (K = 64 hi + 64 lo) ======
__global__ void split_kernel(const float* __restrict__ desc1,
                             const float* __restrict__ desc2) {
    __shared__ float sd[CC][129];
    int b = blockIdx.y;
    int row0 = blockIdx.x * 128;
    int tid = threadIdx.x;   // 256 threads

    for (int i = tid; i < CC * 128; i += 256) {
        int ch = i >> 7, r = i & 127;
        int gr = row0 + r;
        sd[ch][r] = (gr < NN) ? desc1[(size_t)(b * CC + ch) * NN + gr] : 0.f;
    }
    __syncthreads();
    for (int i = tid; i < 128 * KH; i += 256) {
        int r = i >> 7, k = i & 127;
        float v = sd[k & 63][r];
        __half hi = __float2half_rn(v);
        __half o = (k < 64) ? hi : __float2half_rn(v - __half2float(hi));
        g_Ah[((size_t)b * NPAD + row0 + r) * KH + k] = o;
    }
    __syncthreads();

    for (int i = tid; i < CC * 128; i += 256) {
        int ch = i >> 7, r = i & 127;
        int gr = row0 + r;
        sd[ch][r] = (gr < NN) ? desc2[(size_t)(b * CC + ch) * NN + gr] : 0.f;
    }
    __syncthreads();
    for (int i = tid; i < 128 * KH; i += 256) {
        int r = i >> 7, k = i & 127;
        float v = sd[k & 63][r];
        __half hi = __float2half_rn(v);
        __half o = (k < 64) ? hi : __float2half_rn(v - __half2float(hi));
        g_Bh[((size_t)b * NPAD + row0 + r) * KH + k] = o;
    }
}

// ====== Kernel 2: fp16 GEMM, 1 mtile x 2 ntiles, A reused, B pipelined ======
__global__ void __launch_bounds__(128, 2)
mma_kernel(float* __restrict__ out) {
    extern __shared__ char sm[];
    __shared__ int4  s_nb[128];        // absolute neighbor cols for my 128 rows
    __shared__ float s_vs[2][128];
    __shared__ float s_red[2][128];
    __shared__ int   s_last;
    __shared__ float rL[4], rM[4];

    int tid = threadIdx.x;
    int wid = tid >> 5, l = tid & 31;
    int wm = wid & 1, wn = wid >> 1;        // 2 x 2 warp grid
    int ntg = blockIdx.x, mtile = blockIdx.y, b = blockIdx.z;

    uint32_t au = smem_u32(sm);
    const __half* Asrc = g_Ah + ((size_t)b * NPAD + mtile * 128) * KH;

    // group 0: A tile (reused for both ntiles)
#pragma unroll
    for (int tq = 0; tq < 16; ++tq) {
        int i = tq * 128 + tid, rr = i >> 4, g = i & 15;
        cp16(au + rr * ROWB + g * 16, Asrc + (size_t)rr * KH + g * 8);
    }
    CP_COMMIT();
    // groups 1,2: B tiles for ntile = ntg*2 + n
#pragma unroll
    for (int n = 0; n < 2; ++n) {
        const __half* Bsrc = g_Bh + ((size_t)b * NPAD + (ntg * 2 + n) * 128) * KH;
        uint32_t bb = au + (1 + n) * CHUNK;
#pragma unroll
        for (int tq = 0; tq < 16; ++tq) {
            int i = tq * 128 + tid, rr = i >> 4, g = i & 15;
            cp16(bb + rr * ROWB + g * 16, Bsrc + (size_t)rr * KH + g * 8);
        }
        CP_COMMIT();
    }

    // stage neighbor indices + vis while loads fly
    {
        int grow = mtile * 128 + tid;
        int gr = grow < NN ? grow : NN - 1;
        s_nb[tid] = *reinterpret_cast<const int4*>(&g_neigh[((size_t)b * NN + gr) * 4]);
#pragma unroll
        for (int n = 0; n < 2; ++n) {
            int gcol = (ntg * 2 + n) * 128 + tid;
            s_vs[n][tid] = (gcol < NN) ? g_visNeg[b * NN + gcol] : NEGBIG;
        }
    }

    // ldmatrix per-lane row offsets (warp tile 64x64)
    int lane7 = l & 7, mat = l >> 3, kh = mat >> 1;
    uint32_t arow[4], brow[4];
#pragma unroll
    for (int mf = 0; mf < 4; ++mf)
        arow[mf] = (uint32_t)(wm * 64 + mf * 16 + (mat & 1) * 8 + lane7) * ROWB;
#pragma unroll
    for (int bf = 0; bf < 4; ++bf)
        brow[bf] = (uint32_t)(wn * 64 + bf * 16 + (mat & 1) * 8 + lane7) * ROWB;

    float mrow[4][2];   // per (mf, half) running max across both ntiles? no: per tile
    // process the two ntiles sequentially
#pragma unroll
    for (int n = 0; n < 2; ++n) {
        if (n == 0) CP_WAIT(1);   // A + B0 landed (B1 still streaming)
        else        CP_WAIT(0);   // B1 landed
        __syncthreads();

        float cfr[4][8][4];
#pragma unroll
        for (int mf = 0; mf < 4; ++mf)
#pragma unroll
            for (int nf = 0; nf < 8; ++nf)
#pragma unroll
                for (int q = 0; q < 4; ++q) cfr[mf][nf][q] = 0.f;

        uint32_t bbase = au + (1 + n) * CHUNK;
#pragma unroll
        for (int ks = 0; ks < 8; ++ks) {
            uint32_t g16 = (uint32_t)((ks * 2 + kh) << 4);
            uint32_t af[4][4], bq[4][4];
#pragma unroll
            for (int mf = 0; mf < 4; ++mf) ldsm4(af[mf], au + arow[mf] + g16);
#pragma unroll
            for (int bf = 0; bf < 4; ++bf) ldsm4(bq[bf], bbase + brow[bf] + g16);
#pragma unroll
            for (int mf = 0; mf < 4; ++mf)
#pragma unroll
                for (int nf = 0; nf < 8; ++nf)
                    mma16816(cfr[mf][nf], af[mf],
                             bq[nf >> 1][nf & 1], bq[nf >> 1][2 + (nf & 1)]);
        }

        // epilogue for this ntile: vis add + neighbor-masked max per row
        int colbase = (ntg * 2 + n) * 128;
#pragma unroll
        for (int mf = 0; mf < 4; ++mf) {
#pragma unroll
            for (int half = 0; half < 2; ++half) {
                int rl = wm * 64 + mf * 16 + (l >> 2) + half * 8;
                int4 nb = s_nb[rl];
                float mx = NEGBIG;
#pragma unroll
                for (int nf = 0; nf < 8; ++nf) {
                    int lc0 = wn * 64 + nf * 8 + (l & 3) * 2;
                    int gc0 = colbase + lc0, gc1 = gc0 + 1;
                    float v0 = cfr[mf][nf][half * 2 + 0] + s_vs[n][lc0];
                    float v1 = cfr[mf][nf][half * 2 + 1] + s_vs[n][lc0 + 1];
                    bool m0 = (nb.x == gc0) | (nb.y == gc0) | (nb.z == gc0) | (nb.w == gc0);
                    bool m1 = (nb.x == gc1) | (nb.y == gc1) | (nb.z == gc1) | (nb.w == gc1);
                    mx = fmaxf(mx, m0 ? NEGBIG : v0);
                    mx = fmaxf(mx, m1 ? NEGBIG : v1);
                }
                mx = fmaxf(mx, __shfl_xor_sync(0xffffffffu, mx, 1));
                mx = fmaxf(mx, __shfl_xor_sync(0xffffffffu, mx, 2));
                if ((l & 3) == 0) s_red[wn][rl] = mx;
            }
        }
        __syncthreads();
        {
            float m = fmaxf(s_red[0][tid], s_red[1][tid]);
            int grow = mtile * 128 + tid;
            if (grow < NN) {
                float neg = sqrtf(fmaxf(2.f - 2.f * m, EPSF));
                atomicMin(&g_negMinI[b * NN + grow], __float_as_int(neg));
            }
        }
        __syncthreads();
    }
    (void)mrow;

    // last block: deterministic final reduction
    if (tid == 0) {
        __threadfence();
        s_last = (atomicAdd(&g_ctr, 1u) == TOTALB - 1) ? 1 : 0;
    }
    __syncthreads();
    if (s_last) {
        __threadfence();
        float aL = 0.f, aM = 0.f;
        for (int i = tid; i < BQ * NN; i += 128) {
            float neg = __int_as_float(g_negMinI[i]);
            float lv = fmaxf(g_posSim[i] - neg + 1.0f, 0.f);
            float mm = g_match[i];
            aL += lv * lv * mm;
            aM += mm;
        }
#pragma unroll
        for (int off = 16; off; off >>= 1) {
            aL += __shfl_xor_sync(0xffffffffu, aL, off);
            aM += __shfl_xor_sync(0xffffffffu, aM, off);
        }
        if (l == 0) { rL[wid] = aL; rM[wid] = aM; }
        __syncthreads();
        if (tid == 0) {
            float sL = 0.f, sM = 0.f;
#pragma unroll
            for (int q = 0; q < 4; ++q) { sL += rL[q]; sM += rM[q]; }
            out[0] = sL / sM;
        }
    }
}

// ---------------- launch ----------------
extern "C" void kernel_launch(void* const* d_in, const int* in_sizes, int n_in,
                              void* d_out, int out_size) {
    // metadata order: score1, score2, desc1, desc2, homo12, homo21
    const float* desc1  = (const float*)d_in[2];
    const float* desc2  = (const float*)d_in[3];
    const float* homo12 = (const float*)d_in[4];
    const float* homo21 = (const float*)d_in[5];

    cudaFuncSetAttribute(mma_kernel, cudaFuncAttributeMaxDynamicSharedMemorySize,
                         SMEM_BYTES);
    prep_kernel<<<(BQ * NN * 8 + 255) / 256, 256>>>(desc1, desc2, homo12, homo21);
    split_kernel<<<dim3(MT, BQ), 256>>>(desc1, desc2);
    dim3 g(NTG, MT, BQ);
    mma_kernel<<<g, 128, SMEM_BYTES>>>((float*)d_out);
}